// round 6
// baseline (speedup 1.0000x reference)
#include <cuda_runtime.h>
#include <cuda_fp16.h>
#include <cstdint>
#include <cmath>

#define T_SEQ   1024
#define D_MODEL 1024
#define NHEAD   16
#define HDIM    64
#define DFF     4096
#define BATCH   8
#define MROWS   (BATCH * T_SEQ)
#define QKV_N   (3 * D_MODEL)

// ---------------- scratch (device globals: allocation-free) ----------------
__device__ __half g_h1 [(size_t)MROWS * D_MODEL];
__device__ __half g_qkv[(size_t)MROWS * QKV_N];
__device__ __half g_att[(size_t)MROWS * D_MODEL];
__device__ float  g_res[(size_t)MROWS * D_MODEL];
__device__ __half g_ff [(size_t)MROWS * DFF];
__device__ __half g_wqkvT[(size_t)QKV_N * D_MODEL];
__device__ __half g_woT[(size_t)D_MODEL * D_MODEL];
__device__ __half g_w1T[(size_t)DFF * D_MODEL];
__device__ __half g_w2T[(size_t)D_MODEL * DFF];
__device__ float  g_bqkv[QKV_N];

// ---------------- helpers ----------------
__device__ __forceinline__ uint32_t smem_u32(const void* p) {
    uint32_t a;
    asm("{ .reg .u64 t; cvta.to.shared.u64 t, %1; cvt.u32.u64 %0, t; }" : "=r"(a) : "l"(p));
    return a;
}
__device__ __forceinline__ float warp_sum(float v) {
#pragma unroll
    for (int o = 16; o > 0; o >>= 1) v += __shfl_xor_sync(0xffffffffu, v, o);
    return v;
}
__device__ __forceinline__ float fast_ex2(float x) {
    float y; asm("ex2.approx.f32 %0, %1;" : "=f"(y) : "f"(x)); return y;
}
__device__ __forceinline__ float fast_tanh(float x) {
    float y; asm("tanh.approx.f32 %0, %1;" : "=f"(y) : "f"(x)); return y;
}
__device__ __forceinline__ float gelu_tanh(float x) {
    float x3 = x * x * x;
    float u  = 0.7978845608028654f * (x + 0.044715f * x3);
    return 0.5f * x * (1.0f + fast_tanh(u));
}
__device__ __forceinline__ void mma_f16(float* c, const uint32_t* a, uint32_t b0, uint32_t b1) {
    asm volatile(
        "mma.sync.aligned.m16n8k16.row.col.f32.f16.f16.f32 "
        "{%0,%1,%2,%3}, {%4,%5,%6,%7}, {%8,%9}, {%0,%1,%2,%3};\n"
        : "+f"(c[0]), "+f"(c[1]), "+f"(c[2]), "+f"(c[3])
        : "r"(a[0]), "r"(a[1]), "r"(a[2]), "r"(a[3]), "r"(b0), "r"(b1));
}
__device__ __forceinline__ void ldsm4(uint32_t* r, uint32_t addr) {
    asm volatile("ldmatrix.sync.aligned.m8n8.x4.shared.b16 {%0,%1,%2,%3}, [%4];"
        : "=r"(r[0]), "=r"(r[1]), "=r"(r[2]), "=r"(r[3]) : "r"(addr));
}
__device__ __forceinline__ uint32_t f22h2(float lo, float hi) {
    uint32_t u;
    asm("cvt.rn.f16x2.f32 %0, %1, %2;" : "=r"(u) : "f"(hi), "f"(lo));
    return u;
}
__device__ __forceinline__ void cp16(uint32_t dst, const void* src) {
    asm volatile("cp.async.cg.shared.global [%0], [%1], 16;" :: "r"(dst), "l"(src));
}
#define CP_COMMIT() asm volatile("cp.async.commit_group;" ::: "memory")
#define CP_WAIT1()  asm volatile("cp.async.wait_group 1;" ::: "memory")
#define CP_WAIT0()  asm volatile("cp.async.wait_group 0;" ::: "memory")

// ---------------- weight transpose -> half: out[C][R] = (half)in[R][C] ----
__global__ __launch_bounds__(256) void transpose_h_kernel(
    const float* __restrict__ in, __half* __restrict__ out, int R, int C)
{
    __shared__ float t[32][33];
    const int bx = blockIdx.x * 32, by = blockIdx.y * 32;
    const int tx = threadIdx.x, ty = threadIdx.y;  // (32, 8)
#pragma unroll
    for (int i = 0; i < 4; i++)
        t[ty + 8 * i][tx] = in[(size_t)(by + ty + 8 * i) * C + bx + tx];
    __syncthreads();
#pragma unroll
    for (int i = 0; i < 4; i++)
        out[(size_t)(bx + ty + 8 * i) * R + by + tx] = __float2half_rn(t[tx][ty + 8 * i]);
}

__global__ void bias_concat_kernel(const float* __restrict__ bq,
                                   const float* __restrict__ bk,
                                   const float* __restrict__ bv,
                                   float* __restrict__ o)
{
    const int i = blockIdx.x * 256 + threadIdx.x;
    o[i] = (i < D_MODEL) ? bq[i] : (i < 2 * D_MODEL) ? bk[i - D_MODEL] : bv[i - 2 * D_MODEL];
}

// ---------------- LayerNorm (f32 in -> half out) ----------------
__global__ __launch_bounds__(256) void ln_kernel(
    const float* __restrict__ x, const float* __restrict__ sc,
    const float* __restrict__ bi, __half* __restrict__ y)
{
    __shared__ float redm[8], redv[8], bcast[2];
    const int row = blockIdx.x, tid = threadIdx.x;
    const int wid = tid >> 5, lane = tid & 31;

    float4 v = *(const float4*)&x[(size_t)row * D_MODEL + tid * 4];
    float s = warp_sum(v.x + v.y + v.z + v.w);
    if (lane == 0) redm[wid] = s;
    __syncthreads();
    if (tid == 0) {
        float tot = 0.f;
#pragma unroll
        for (int i = 0; i < 8; i++) tot += redm[i];
        bcast[0] = tot * (1.0f / 1024.0f);
    }
    __syncthreads();
    const float mean = bcast[0];
    float dx = v.x - mean, dy = v.y - mean, dz = v.z - mean, dw = v.w - mean;
    float ss = warp_sum(dx * dx + dy * dy + dz * dz + dw * dw);
    if (lane == 0) redv[wid] = ss;
    __syncthreads();
    if (tid == 0) {
        float tot = 0.f;
#pragma unroll
        for (int i = 0; i < 8; i++) tot += redv[i];
        bcast[1] = rsqrtf(tot * (1.0f / 1024.0f) + 1e-6f);
    }
    __syncthreads();
    const float rstd = bcast[1];
    float4 scv = *(const float4*)&sc[tid * 4];
    float4 biv = *(const float4*)&bi[tid * 4];
    __half2* yp = (__half2*)&y[(size_t)row * D_MODEL + tid * 4];
    yp[0] = __floats2half2_rn(dx * rstd * scv.x + biv.x, dy * rstd * scv.y + biv.y);
    yp[1] = __floats2half2_rn(dz * rstd * scv.z + biv.z, dw * rstd * scv.w + biv.w);
}

// ---------------- fp16 GEMM, 256x128 CTA tile, cp.async double-buffered ----
// C = A[M,K] @ Bt[N,K]^T + bias; EPI: 1 = f32 +res, 2 = half gelu, 3 = half
// 8 warps in 4x2, warp tile 64x64; k-chunk 64 halves; 2 stages.
#define ASTG 9216  // uint32 per A stage: 256 rows x 36
#define BSTG 4608  // uint32 per B stage: 128 rows x 36
#define GEMM_SMEM ((2 * ASTG + 2 * BSTG) * 4)  // 110592 bytes

template <int EPI>
__global__ __launch_bounds__(256) void gemm_h_kernel(
    const __half* __restrict__ A, const __half* __restrict__ Bt,
    const float* __restrict__ bias, const float* __restrict__ res,
    void* __restrict__ Cv, int M, int N, int K)
{
    extern __shared__ uint32_t smh[];
    const uint32_t smb = smem_u32(smh);
    const int tid = threadIdx.x;
    const int wid = tid >> 5, lane = tid & 31;
    const int g = lane >> 2, t = lane & 3;
    const int mi = lane >> 3, mr = lane & 7;
    const int rowoff = (mi & 1) * 8, koff = (mi >> 1) * 4;  // uint32 units
    const int warpM = (wid >> 1) * 64, warpN = (wid & 1) * 64;
    const int bm = blockIdx.y * 256, bn = blockIdx.x * 128;
    const int nch = K >> 6;

    const __half* Ab = A + (size_t)bm * K;
    const __half* Bb = Bt + (size_t)bn * K;
    const int crow = tid >> 3, cp = tid & 7;  // A fill: 8 iters; B fill: 4 iters

    // preload chunk 0 into stage 0
    {
#pragma unroll
        for (int r = 0; r < 8; r++) {
            const int row = crow + 32 * r;
            cp16(smb + (uint32_t)(row * 36 + cp * 4) * 4, Ab + (size_t)row * K + cp * 8);
        }
#pragma unroll
        for (int r = 0; r < 4; r++) {
            const int row = crow + 32 * r;
            cp16(smb + (uint32_t)(2 * ASTG + row * 36 + cp * 4) * 4, Bb + (size_t)row * K + cp * 8);
        }
        CP_COMMIT();
    }

    float c[4][8][4];
#pragma unroll
    for (int i = 0; i < 4; i++)
#pragma unroll
        for (int j = 0; j < 8; j++)
#pragma unroll
            for (int q = 0; q < 4; q++) c[i][j][q] = 0.f;

    for (int ch = 0; ch < nch; ch++) {
        const int s = ch & 1;
        if (ch + 1 < nch) {
            const int k0 = (ch + 1) << 6;
            const uint32_t ao = (uint32_t)((s ^ 1) * ASTG) * 4;
            const uint32_t bo = (uint32_t)(2 * ASTG + (s ^ 1) * BSTG) * 4;
#pragma unroll
            for (int r = 0; r < 8; r++) {
                const int row = crow + 32 * r;
                cp16(smb + ao + (uint32_t)(row * 36 + cp * 4) * 4, Ab + (size_t)row * K + k0 + cp * 8);
            }
#pragma unroll
            for (int r = 0; r < 4; r++) {
                const int row = crow + 32 * r;
                cp16(smb + bo + (uint32_t)(row * 36 + cp * 4) * 4, Bb + (size_t)row * K + k0 + cp * 8);
            }
            CP_COMMIT();
            CP_WAIT1();
        } else {
            CP_WAIT0();
        }
        __syncthreads();

        const uint32_t Ast = smb + (uint32_t)(s * ASTG) * 4;
        const uint32_t Bst = smb + (uint32_t)(2 * ASTG + s * BSTG) * 4;

        // hoist all A fragments for this chunk (64 regs)
        uint32_t af[4][4][4];
#pragma unroll
        for (int i = 0; i < 4; i++) {
            const uint32_t aa = Ast + (uint32_t)((warpM + 16 * i + rowoff + mr) * 36 + koff) * 4;
#pragma unroll
            for (int km = 0; km < 4; km++) ldsm4(af[i][km], aa + km * 32u);
        }
        // per n-tile: load B frags (short live range), fire 16 mma
#pragma unroll
        for (int j = 0; j < 8; j++) {
            uint32_t bf[8];
            const uint32_t ab = Bst + (uint32_t)((warpN + 8 * j + mr) * 36 + mi * 4) * 4;
            ldsm4(bf, ab);
            ldsm4(bf + 4, ab + 64);
#pragma unroll
            for (int i = 0; i < 4; i++) {
                mma_f16(c[i][j], af[i][0], bf[0], bf[1]);
                mma_f16(c[i][j], af[i][1], bf[2], bf[3]);
                mma_f16(c[i][j], af[i][2], bf[4], bf[5]);
                mma_f16(c[i][j], af[i][3], bf[6], bf[7]);
            }
        }
        __syncthreads();
    }

    // epilogue: warp tile rows bm+warpM+16i+{g,g+8}, cols bn+warpN+8j+2t
#pragma unroll
    for (int i = 0; i < 4; i++) {
#pragma unroll
        for (int j = 0; j < 8; j++) {
            const int row0 = bm + warpM + 16 * i + g;
            const int col  = bn + warpN + 8 * j + 2 * t;
            const float b0 = bias[col], b1 = bias[col + 1];
            float v00 = c[i][j][0] + b0, v01 = c[i][j][1] + b1;
            float v10 = c[i][j][2] + b0, v11 = c[i][j][3] + b1;
            if (EPI == 1) {
                float* C = (float*)Cv;
                float2 r0 = *(const float2*)&res[(size_t)row0 * N + col];
                float2 r1 = *(const float2*)&res[(size_t)(row0 + 8) * N + col];
                *(float2*)&C[(size_t)row0 * N + col]       = make_float2(v00 + r0.x, v01 + r0.y);
                *(float2*)&C[(size_t)(row0 + 8) * N + col] = make_float2(v10 + r1.x, v11 + r1.y);
            } else if (EPI == 2) {
                __half* C = (__half*)Cv;
                *(__half2*)&C[(size_t)row0 * N + col] =
                    __floats2half2_rn(gelu_tanh(v00), gelu_tanh(v01));
                *(__half2*)&C[(size_t)(row0 + 8) * N + col] =
                    __floats2half2_rn(gelu_tanh(v10), gelu_tanh(v11));
            } else {  // EPI == 3
                __half* C = (__half*)Cv;
                *(__half2*)&C[(size_t)row0 * N + col]       = __floats2half2_rn(v00, v01);
                *(__half2*)&C[(size_t)(row0 + 8) * N + col] = __floats2half2_rn(v10, v11);
            }
        }
    }
}

// ---------------- tensor-core causal flash attention (fp16 mma, fp32 accum) ----
__global__ __launch_bounds__(256, 2) void attn_tc_kernel(
    const __half* __restrict__ QKV, __half* __restrict__ Oh)
{
    __shared__ uint32_t Qs[128][36];
    __shared__ uint32_t Ks[64][36];
    __shared__ uint32_t Vt[64][36];

    const int qt  = (int)gridDim.x - 1 - (int)blockIdx.x;
    const int bh  = blockIdx.y;
    const int b   = bh >> 4, h = bh & 15;
    const int tid = threadIdx.x, wid = tid >> 5, lane = tid & 31;
    const int g = lane >> 2, t = lane & 3;
    const int qb = qt * 128;
    const size_t bb = (size_t)b * T_SEQ;
    const int hq = h * HDIM, hk = hq + D_MODEL, hv = hq + 2 * D_MODEL;
    const int r0 = wid * 16;

#pragma unroll
    for (int r = 0; r < 4; r++) {
        const int lin = tid + 256 * r;
        const int row = lin >> 3, c = lin & 7;
        *(uint4*)&Qs[row][4 * c] =
            *(const uint4*)&QKV[(bb + qb + row) * QKV_N + hq + 8 * c];
    }
    __syncthreads();

    uint32_t qa[4][4];
    {
        const uint32_t qbase = smem_u32(Qs);
        const int mi = lane >> 3, mr = lane & 7;
        const int rowoff = (mi & 1) * 8, koff = (mi >> 1) * 4;
#pragma unroll
        for (int km = 0; km < 4; km++)
            ldsm4(qa[km], qbase + (uint32_t)((r0 + rowoff + mr) * 36 + km * 8 + koff) * 4);
    }

    float o[8][4];
#pragma unroll
    for (int j = 0; j < 8; j++)
#pragma unroll
        for (int q = 0; q < 4; q++) o[j][q] = 0.f;
    float m_g = -1e30f, m_g8 = -1e30f, l_g = 0.f, l_g8 = 0.f;
    const float SC = 0.18033688011112042f;  // (1/8) * log2(e)

    const uint32_t kbase = smem_u32(Ks), vbase = smem_u32(Vt);
    const int mi = lane >> 3, mr = lane & 7;

    const int nkt = 2 * qt + 2;
    for (int kt = 0; kt < nkt; kt++) {
        const int k0 = kt * 64;
#pragma unroll
        for (int r = 0; r < 2; r++) {
            const int lin = tid + 256 * r;
            const int row = lin >> 3, c = lin & 7;
            *(uint4*)&Ks[row][4 * c] =
                *(const uint4*)&QKV[(bb + k0 + row) * QKV_N + hk + 8 * c];
        }
        {
            const int kp = tid & 31, d8 = (tid >> 5) * 8;
            const __half* v0p = &QKV[(bb + k0 + 2 * kp) * QKV_N + hv + d8];
            uint4 v0 = *(const uint4*)v0p;
            uint4 v1 = *(const uint4*)(v0p + QKV_N);
            const ushort* a0 = (const ushort*)&v0;
            const ushort* a1 = (const ushort*)&v1;
#pragma unroll
            for (int i = 0; i < 8; i++)
                Vt[d8 + i][kp] = (uint32_t)a0[i] | ((uint32_t)a1[i] << 16);
        }
        __syncthreads();

        float s[8][4];
#pragma unroll
        for (int j = 0; j < 8; j++) {
            uint32_t kb[8];
            const uint32_t ab = kbase + (uint32_t)((8 * j + mr) * 36 + mi * 4) * 4;
            ldsm4(kb, ab);
            ldsm4(kb + 4, ab + 64);
            s[j][0] = s[j][1] = s[j][2] = s[j][3] = 0.f;
            mma_f16(s[j], qa[0], kb[0], kb[1]);
            mma_f16(s[j], qa[1], kb[2], kb[3]);
            mma_f16(s[j], qa[2], kb[4], kb[5]);
            mma_f16(s[j], qa[3], kb[6], kb[7]);
        }

        if (kt >= 2 * qt) {
            const int rg = qb + r0 + g;
#pragma unroll
            for (int j = 0; j < 8; j++) {
                const int col = k0 + 8 * j + 2 * t;
                if (col     > rg)     s[j][0] = -1e30f;
                if (col + 1 > rg)     s[j][1] = -1e30f;
                if (col     > rg + 8) s[j][2] = -1e30f;
                if (col + 1 > rg + 8) s[j][3] = -1e30f;
            }
        }

        float mg = -1e30f, mg8 = -1e30f;
#pragma unroll
        for (int j = 0; j < 8; j++) {
            mg  = fmaxf(mg,  fmaxf(s[j][0], s[j][1]));
            mg8 = fmaxf(mg8, fmaxf(s[j][2], s[j][3]));
        }
        mg  = fmaxf(mg,  __shfl_xor_sync(0xffffffffu, mg, 1));
        mg  = fmaxf(mg,  __shfl_xor_sync(0xffffffffu, mg, 2));
        mg8 = fmaxf(mg8, __shfl_xor_sync(0xffffffffu, mg8, 1));
        mg8 = fmaxf(mg8, __shfl_xor_sync(0xffffffffu, mg8, 2));
        const float mng  = fmaxf(m_g, mg);
        const float mng8 = fmaxf(m_g8, mg8);
        const float corr  = fast_ex2((m_g  - mng)  * SC);
        const float corr8 = fast_ex2((m_g8 - mng8) * SC);
        float sg = 0.f, sg8 = 0.f;
#pragma unroll
        for (int j = 0; j < 8; j++) {
            s[j][0] = fast_ex2((s[j][0] - mng)  * SC);
            s[j][1] = fast_ex2((s[j][1] - mng)  * SC);
            s[j][2] = fast_ex2((s[j][2] - mng8) * SC);
            s[j][3] = fast_ex2((s[j][3] - mng8) * SC);
            sg  += s[j][0] + s[j][1];
            sg8 += s[j][2] + s[j][3];
        }
        sg  += __shfl_xor_sync(0xffffffffu, sg, 1);
        sg  += __shfl_xor_sync(0xffffffffu, sg, 2);
        sg8 += __shfl_xor_sync(0xffffffffu, sg8, 1);
        sg8 += __shfl_xor_sync(0xffffffffu, sg8, 2);
        l_g  = l_g  * corr  + sg;
        l_g8 = l_g8 * corr8 + sg8;
        m_g = mng; m_g8 = mng8;
#pragma unroll
        for (int j = 0; j < 8; j++) {
            o[j][0] *= corr;  o[j][1] *= corr;
            o[j][2] *= corr8; o[j][3] *= corr8;
        }

        uint32_t pa[4][4];
#pragma unroll
        for (int km = 0; km < 4; km++) {
            pa[km][0] = f22h2(s[2 * km][0], s[2 * km][1]);
            pa[km][1] = f22h2(s[2 * km][2], s[2 * km][3]);
            pa[km][2] = f22h2(s[2 * km + 1][0], s[2 * km + 1][1]);
            pa[km][3] = f22h2(s[2 * km + 1][2], s[2 * km + 1][3]);
        }

#pragma unroll
        for (int j = 0; j < 8; j++) {
            uint32_t vb[8];
            const uint32_t ab = vbase + (uint32_t)((8 * j + mr) * 36 + mi * 4) * 4;
            ldsm4(vb, ab);
            ldsm4(vb + 4, ab + 64);
            mma_f16(o[j], pa[0], vb[0], vb[1]);
            mma_f16(o[j], pa[1], vb[2], vb[3]);
            mma_f16(o[j], pa[2], vb[4], vb[5]);
            mma_f16(o[j], pa[3], vb[6], vb[7]);
        }
        __syncthreads();
    }

    const float ig = 1.0f / l_g, ig8 = 1.0f / l_g8;
    __half* Og = Oh + (bb + qb + r0) * D_MODEL + hq;
#pragma unroll
    for (int j = 0; j < 8; j++) {
        const int col = 8 * j + 2 * t;
        *(__half2*)&Og[(size_t)g * D_MODEL + col] =
            __floats2half2_rn(o[j][0] * ig, o[j][1] * ig);
        *(__half2*)&Og[(size_t)(g + 8) * D_MODEL + col] =
            __floats2half2_rn(o[j][2] * ig8, o[j][3] * ig8);
    }
}

// ---------------- launch ----------------
extern "C" void kernel_launch(void* const* d_in, const int* in_sizes, int n_in,
                              void* d_out, int out_size)
{
    const float* x    = (const float*)d_in[0];
    const float* ln1s = (const float*)d_in[2];
    const float* ln1b = (const float*)d_in[3];
    const float* wq = (const float*)d_in[4];  const float* bq = (const float*)d_in[5];
    const float* wk = (const float*)d_in[6];  const float* bk = (const float*)d_in[7];
    const float* wv = (const float*)d_in[8];  const float* bv = (const float*)d_in[9];
    const float* wo = (const float*)d_in[10]; const float* bo = (const float*)d_in[11];
    const float* ln2s = (const float*)d_in[12];
    const float* ln2b = (const float*)d_in[13];
    const float* w1 = (const float*)d_in[14]; const float* b1 = (const float*)d_in[15];
    const float* w2 = (const float*)d_in[16]; const float* b2 = (const float*)d_in[17];
    float* out = (float*)d_out;

    __half *h1, *qkv, *att, *ff, *wqkvT, *woT, *w1T, *w2T;
    float *res, *bqkv;
    cudaGetSymbolAddress((void**)&h1,   g_h1);
    cudaGetSymbolAddress((void**)&qkv,  g_qkv);
    cudaGetSymbolAddress((void**)&att,  g_att);
    cudaGetSymbolAddress((void**)&res,  g_res);
    cudaGetSymbolAddress((void**)&ff,   g_ff);
    cudaGetSymbolAddress((void**)&wqkvT, g_wqkvT);
    cudaGetSymbolAddress((void**)&woT,  g_woT);
    cudaGetSymbolAddress((void**)&w1T,  g_w1T);
    cudaGetSymbolAddress((void**)&w2T,  g_w2T);
    cudaGetSymbolAddress((void**)&bqkv, g_bqkv);

    cudaFuncSetAttribute(gemm_h_kernel<1>, cudaFuncAttributeMaxDynamicSharedMemorySize, GEMM_SMEM);
    cudaFuncSetAttribute(gemm_h_kernel<2>, cudaFuncAttributeMaxDynamicSharedMemorySize, GEMM_SMEM);
    cudaFuncSetAttribute(gemm_h_kernel<3>, cudaFuncAttributeMaxDynamicSharedMemorySize, GEMM_SMEM);

    const dim3 tb(32, 8);
    transpose_h_kernel<<<dim3(D_MODEL / 32, D_MODEL / 32), tb>>>(wq, wqkvT, D_MODEL, D_MODEL);
    transpose_h_kernel<<<dim3(D_MODEL / 32, D_MODEL / 32), tb>>>(wk, wqkvT + (size_t)D_MODEL * D_MODEL, D_MODEL, D_MODEL);
    transpose_h_kernel<<<dim3(D_MODEL / 32, D_MODEL / 32), tb>>>(wv, wqkvT + (size_t)2 * D_MODEL * D_MODEL, D_MODEL, D_MODEL);
    transpose_h_kernel<<<dim3(D_MODEL / 32, D_MODEL / 32), tb>>>(wo, woT, D_MODEL, D_MODEL);
    transpose_h_kernel<<<dim3(DFF / 32, D_MODEL / 32), tb>>>(w1, w1T, D_MODEL, DFF);
    transpose_h_kernel<<<dim3(D_MODEL / 32, DFF / 32), tb>>>(w2, w2T, DFF, D_MODEL);
    bias_concat_kernel<<<QKV_N / 256, 256>>>(bq, bk, bv, bqkv);

    const dim3 gQKV(QKV_N / 128, MROWS / 256);   // (24, 32)
    const dim3 gD(D_MODEL / 128, MROWS / 256);   // (8, 32)
    const dim3 gF(DFF / 128,     MROWS / 256);   // (32, 32)

    ln_kernel<<<MROWS, 256>>>(x, ln1s, ln1b, h1);
    gemm_h_kernel<3><<<gQKV, 256, GEMM_SMEM>>>(h1, wqkvT, bqkv, nullptr, qkv, MROWS, QKV_N, D_MODEL);
    attn_tc_kernel<<<dim3(T_SEQ / 128, BATCH * NHEAD), 256>>>(qkv, att);
    gemm_h_kernel<1><<<gD, 256, GEMM_SMEM>>>(att, woT, bo, x, res, MROWS, D_MODEL, D_MODEL);
    ln_kernel<<<MROWS, 256>>>(res, ln2s, ln2b, h1);
    gemm_h_kernel<2><<<gF, 256, GEMM_SMEM>>>(h1, w1T, b1, nullptr, ff, MROWS, DFF, D_MODEL);
    gemm_h_kernel<1><<<gD, 256, GEMM_SMEM>>>(ff, w2T, b2, res, out, MROWS, D_MODEL, DFF);
}

// round 7
// speedup vs baseline: 1.0469x; 1.0469x over previous
#include <cuda_runtime.h>
#include <cuda_fp16.h>
#include <cstdint>
#include <cmath>

#define T_SEQ   1024
#define D_MODEL 1024
#define NHEAD   16
#define HDIM    64
#define DFF     4096
#define BATCH   8
#define MROWS   (BATCH * T_SEQ)
#define QKV_N   (3 * D_MODEL)

// ---------------- scratch (device globals: allocation-free) ----------------
__device__ __half g_h1 [(size_t)MROWS * D_MODEL];
__device__ __half g_qkv[(size_t)MROWS * QKV_N];
__device__ __half g_att[(size_t)MROWS * D_MODEL];
__device__ float  g_res[(size_t)MROWS * D_MODEL];
__device__ __half g_ff [(size_t)MROWS * DFF];
__device__ __half g_wqkvT[(size_t)QKV_N * D_MODEL];
__device__ __half g_woT[(size_t)D_MODEL * D_MODEL];
__device__ __half g_w1T[(size_t)DFF * D_MODEL];
__device__ __half g_w2T[(size_t)D_MODEL * DFF];
__device__ float  g_bqkv[QKV_N];

// ---------------- helpers ----------------
__device__ __forceinline__ uint32_t smem_u32(const void* p) {
    uint32_t a;
    asm("{ .reg .u64 t; cvta.to.shared.u64 t, %1; cvt.u32.u64 %0, t; }" : "=r"(a) : "l"(p));
    return a;
}
__device__ __forceinline__ float warp_sum(float v) {
#pragma unroll
    for (int o = 16; o > 0; o >>= 1) v += __shfl_xor_sync(0xffffffffu, v, o);
    return v;
}
__device__ __forceinline__ float fast_ex2(float x) {
    float y; asm("ex2.approx.f32 %0, %1;" : "=f"(y) : "f"(x)); return y;
}
__device__ __forceinline__ float fast_tanh(float x) {
    float y; asm("tanh.approx.f32 %0, %1;" : "=f"(y) : "f"(x)); return y;
}
__device__ __forceinline__ float gelu_tanh(float x) {
    float x3 = x * x * x;
    float u  = 0.7978845608028654f * (x + 0.044715f * x3);
    return 0.5f * x * (1.0f + fast_tanh(u));
}
__device__ __forceinline__ void mma_f16(float* c, const uint32_t* a, uint32_t b0, uint32_t b1) {
    asm volatile(
        "mma.sync.aligned.m16n8k16.row.col.f32.f16.f16.f32 "
        "{%0,%1,%2,%3}, {%4,%5,%6,%7}, {%8,%9}, {%0,%1,%2,%3};\n"
        : "+f"(c[0]), "+f"(c[1]), "+f"(c[2]), "+f"(c[3])
        : "r"(a[0]), "r"(a[1]), "r"(a[2]), "r"(a[3]), "r"(b0), "r"(b1));
}
__device__ __forceinline__ void ldsm4(uint32_t* r, uint32_t addr) {
    asm volatile("ldmatrix.sync.aligned.m8n8.x4.shared.b16 {%0,%1,%2,%3}, [%4];"
        : "=r"(r[0]), "=r"(r[1]), "=r"(r[2]), "=r"(r[3]) : "r"(addr));
}
__device__ __forceinline__ uint32_t f22h2(float lo, float hi) {
    uint32_t u;
    asm("cvt.rn.f16x2.f32 %0, %1, %2;" : "=r"(u) : "f"(hi), "f"(lo));
    return u;
}
__device__ __forceinline__ void cp16(uint32_t dst, const void* src) {
    asm volatile("cp.async.cg.shared.global [%0], [%1], 16;" :: "r"(dst), "l"(src));
}
#define CP_COMMIT() asm volatile("cp.async.commit_group;" ::: "memory")
#define CP_WAIT1()  asm volatile("cp.async.wait_group 1;" ::: "memory")
#define CP_WAIT0()  asm volatile("cp.async.wait_group 0;" ::: "memory")

// ---------------- weight transpose -> half: out[C][R] = (half)in[R][C] ----
__global__ __launch_bounds__(256) void transpose_h_kernel(
    const float* __restrict__ in, __half* __restrict__ out, int R, int C)
{
    __shared__ float t[32][33];
    const int bx = blockIdx.x * 32, by = blockIdx.y * 32;
    const int tx = threadIdx.x, ty = threadIdx.y;  // (32, 8)
#pragma unroll
    for (int i = 0; i < 4; i++)
        t[ty + 8 * i][tx] = in[(size_t)(by + ty + 8 * i) * C + bx + tx];
    __syncthreads();
#pragma unroll
    for (int i = 0; i < 4; i++)
        out[(size_t)(bx + ty + 8 * i) * R + by + tx] = __float2half_rn(t[tx][ty + 8 * i]);
}

__global__ void bias_concat_kernel(const float* __restrict__ bq,
                                   const float* __restrict__ bk,
                                   const float* __restrict__ bv,
                                   float* __restrict__ o)
{
    const int i = blockIdx.x * 256 + threadIdx.x;
    o[i] = (i < D_MODEL) ? bq[i] : (i < 2 * D_MODEL) ? bk[i - D_MODEL] : bv[i - 2 * D_MODEL];
}

// ---------------- LayerNorm (f32 in -> half out) ----------------
__global__ __launch_bounds__(256) void ln_kernel(
    const float* __restrict__ x, const float* __restrict__ sc,
    const float* __restrict__ bi, __half* __restrict__ y)
{
    __shared__ float redm[8], redv[8], bcast[2];
    const int row = blockIdx.x, tid = threadIdx.x;
    const int wid = tid >> 5, lane = tid & 31;

    float4 v = *(const float4*)&x[(size_t)row * D_MODEL + tid * 4];
    float s = warp_sum(v.x + v.y + v.z + v.w);
    if (lane == 0) redm[wid] = s;
    __syncthreads();
    if (tid == 0) {
        float tot = 0.f;
#pragma unroll
        for (int i = 0; i < 8; i++) tot += redm[i];
        bcast[0] = tot * (1.0f / 1024.0f);
    }
    __syncthreads();
    const float mean = bcast[0];
    float dx = v.x - mean, dy = v.y - mean, dz = v.z - mean, dw = v.w - mean;
    float ss = warp_sum(dx * dx + dy * dy + dz * dz + dw * dw);
    if (lane == 0) redv[wid] = ss;
    __syncthreads();
    if (tid == 0) {
        float tot = 0.f;
#pragma unroll
        for (int i = 0; i < 8; i++) tot += redv[i];
        bcast[1] = rsqrtf(tot * (1.0f / 1024.0f) + 1e-6f);
    }
    __syncthreads();
    const float rstd = bcast[1];
    float4 scv = *(const float4*)&sc[tid * 4];
    float4 biv = *(const float4*)&bi[tid * 4];
    __half2* yp = (__half2*)&y[(size_t)row * D_MODEL + tid * 4];
    yp[0] = __floats2half2_rn(dx * rstd * scv.x + biv.x, dy * rstd * scv.y + biv.y);
    yp[1] = __floats2half2_rn(dz * rstd * scv.z + biv.z, dw * rstd * scv.w + biv.w);
}

// ---------------- fp16 GEMM, 128x128 CTA tile, 3-stage cp.async ring ----
// C = A[M,K] @ Bt[N,K]^T + bias; EPI: 1 = f32 +res, 2 = half gelu, 3 = half
// 8 warps (2x4), warp tile 64x32; k-chunk 64 halves; 3 stages, 1 sync/chunk.
#define HSTG 4608                     // uint32 per operand per stage (128 x 36)
#define STG_U32 (2 * HSTG)            // uint32 per stage (A + B)
#define GEMM_SMEM (3 * STG_U32 * 4)   // 110592 bytes

template <int EPI>
__global__ __launch_bounds__(256, 2) void gemm_h_kernel(
    const __half* __restrict__ A, const __half* __restrict__ Bt,
    const float* __restrict__ bias, const float* __restrict__ res,
    void* __restrict__ Cv, int M, int N, int K)
{
    extern __shared__ uint32_t smh[];
    const uint32_t smb = smem_u32(smh);
    const int tid = threadIdx.x;
    const int wid = tid >> 5, lane = tid & 31;
    const int g = lane >> 2, t = lane & 3;
    const int mi = lane >> 3, mr = lane & 7;
    const int rowoff = (mi & 1) * 8, koff = (mi >> 1) * 4;  // uint32 units
    const int warpM = (wid >> 2) * 64, warpN = (wid & 3) * 32;
    const int bm = blockIdx.y * 128, bn = blockIdx.x * 128;
    const int nch = K >> 6;

    const __half* Ab = A + (size_t)bm * K;
    const __half* Bb = Bt + (size_t)bn * K;
    const int crow = tid >> 1;                       // 0..127 (fill rows, 2 thr/row)
    const int cpc  = (tid & 1) * 4;                  // piece col: 0 or 4 (x16B)

    // fill one chunk into stage st (each thread: 4 A pieces + 4 B pieces... )
    // mapping: 1024 16B pieces per operand; 256 threads x 4 iterations
    auto fill = [&](int st, int k0) {
        const uint32_t ao = (uint32_t)(st * STG_U32) * 4;
        const uint32_t bo = ao + (uint32_t)HSTG * 4;
#pragma unroll
        for (int r = 0; r < 4; r++) {
            const int idx = tid + 256 * r;
            const int row = idx >> 3, p = idx & 7;
            cp16(smb + ao + (uint32_t)(row * 36 + p * 4) * 4, Ab + (size_t)row * K + k0 + p * 8);
            cp16(smb + bo + (uint32_t)(row * 36 + p * 4) * 4, Bb + (size_t)row * K + k0 + p * 8);
        }
        CP_COMMIT();
    };
    (void)crow; (void)cpc;

    fill(0, 0);
    if (nch > 1) fill(1, 64);

    float c[4][4][4];
#pragma unroll
    for (int i = 0; i < 4; i++)
#pragma unroll
        for (int j = 0; j < 4; j++)
#pragma unroll
            for (int q = 0; q < 4; q++) c[i][j][q] = 0.f;

    int st = 0;   // stage of chunk ch
    for (int ch = 0; ch < nch; ch++) {
        if (ch == nch - 1) { CP_WAIT0(); } else { CP_WAIT1(); }
        __syncthreads();
        if (ch + 2 < nch) {
            int wst = st + 2; if (wst >= 3) wst -= 3;
            fill(wst, (ch + 2) << 6);
        }

        const uint32_t Ast = smb + (uint32_t)(st * STG_U32) * 4;
        const uint32_t Bst = Ast + (uint32_t)HSTG * 4;

        uint32_t bf[4][8];
#pragma unroll
        for (int j = 0; j < 4; j++) {
            const uint32_t ab = Bst + (uint32_t)((warpN + 8 * j + mr) * 36 + mi * 4) * 4;
            ldsm4(bf[j], ab);
            ldsm4(bf[j] + 4, ab + 64);
        }
#pragma unroll
        for (int i = 0; i < 4; i++) {
            uint32_t af[4][4];
            const uint32_t aa = Ast + (uint32_t)((warpM + 16 * i + rowoff + mr) * 36 + koff) * 4;
#pragma unroll
            for (int km = 0; km < 4; km++) ldsm4(af[km], aa + km * 32u);
#pragma unroll
            for (int j = 0; j < 4; j++) {
                mma_f16(c[i][j], af[0], bf[j][0], bf[j][1]);
                mma_f16(c[i][j], af[1], bf[j][2], bf[j][3]);
                mma_f16(c[i][j], af[2], bf[j][4], bf[j][5]);
                mma_f16(c[i][j], af[3], bf[j][6], bf[j][7]);
            }
        }
        if (++st == 3) st = 0;
    }

    // epilogue
#pragma unroll
    for (int i = 0; i < 4; i++) {
#pragma unroll
        for (int j = 0; j < 4; j++) {
            const int row0 = bm + warpM + 16 * i + g;
            const int col  = bn + warpN + 8 * j + 2 * t;
            const float b0 = bias[col], b1 = bias[col + 1];
            float v00 = c[i][j][0] + b0, v01 = c[i][j][1] + b1;
            float v10 = c[i][j][2] + b0, v11 = c[i][j][3] + b1;
            if (EPI == 1) {
                float* C = (float*)Cv;
                float2 r0 = *(const float2*)&res[(size_t)row0 * N + col];
                float2 r1 = *(const float2*)&res[(size_t)(row0 + 8) * N + col];
                *(float2*)&C[(size_t)row0 * N + col]       = make_float2(v00 + r0.x, v01 + r0.y);
                *(float2*)&C[(size_t)(row0 + 8) * N + col] = make_float2(v10 + r1.x, v11 + r1.y);
            } else if (EPI == 2) {
                __half* C = (__half*)Cv;
                *(__half2*)&C[(size_t)row0 * N + col] =
                    __floats2half2_rn(gelu_tanh(v00), gelu_tanh(v01));
                *(__half2*)&C[(size_t)(row0 + 8) * N + col] =
                    __floats2half2_rn(gelu_tanh(v10), gelu_tanh(v11));
            } else {  // EPI == 3
                __half* C = (__half*)Cv;
                *(__half2*)&C[(size_t)row0 * N + col]       = __floats2half2_rn(v00, v01);
                *(__half2*)&C[(size_t)(row0 + 8) * N + col] = __floats2half2_rn(v10, v11);
            }
        }
    }
}

// ---------------- tensor-core causal flash attention (fp16 mma, fp32 accum) ----
__global__ __launch_bounds__(256, 2) void attn_tc_kernel(
    const __half* __restrict__ QKV, __half* __restrict__ Oh)
{
    __shared__ uint32_t Qs[128][36];
    __shared__ uint32_t Ks[64][36];
    __shared__ uint32_t Vt[64][36];

    const int qt  = (int)gridDim.x - 1 - (int)blockIdx.x;
    const int bh  = blockIdx.y;
    const int b   = bh >> 4, h = bh & 15;
    const int tid = threadIdx.x, wid = tid >> 5, lane = tid & 31;
    const int g = lane >> 2, t = lane & 3;
    const int qb = qt * 128;
    const size_t bb = (size_t)b * T_SEQ;
    const int hq = h * HDIM, hk = hq + D_MODEL, hv = hq + 2 * D_MODEL;
    const int r0 = wid * 16;

#pragma unroll
    for (int r = 0; r < 4; r++) {
        const int lin = tid + 256 * r;
        const int row = lin >> 3, c = lin & 7;
        *(uint4*)&Qs[row][4 * c] =
            *(const uint4*)&QKV[(bb + qb + row) * QKV_N + hq + 8 * c];
    }
    __syncthreads();

    uint32_t qa[4][4];
    {
        const uint32_t qbase = smem_u32(Qs);
        const int mi = lane >> 3, mr = lane & 7;
        const int rowoff = (mi & 1) * 8, koff = (mi >> 1) * 4;
#pragma unroll
        for (int km = 0; km < 4; km++)
            ldsm4(qa[km], qbase + (uint32_t)((r0 + rowoff + mr) * 36 + km * 8 + koff) * 4);
    }

    float o[8][4];
#pragma unroll
    for (int j = 0; j < 8; j++)
#pragma unroll
        for (int q = 0; q < 4; q++) o[j][q] = 0.f;
    float m_g = -1e30f, m_g8 = -1e30f, l_g = 0.f, l_g8 = 0.f;
    const float SC = 0.18033688011112042f;  // (1/8) * log2(e)

    const uint32_t kbase = smem_u32(Ks), vbase = smem_u32(Vt);
    const int mi = lane >> 3, mr = lane & 7;

    const int nkt = 2 * qt + 2;
    for (int kt = 0; kt < nkt; kt++) {
        const int k0 = kt * 64;
#pragma unroll
        for (int r = 0; r < 2; r++) {
            const int lin = tid + 256 * r;
            const int row = lin >> 3, c = lin & 7;
            *(uint4*)&Ks[row][4 * c] =
                *(const uint4*)&QKV[(bb + k0 + row) * QKV_N + hk + 8 * c];
        }
        {
            const int kp = tid & 31, d8 = (tid >> 5) * 8;
            const __half* v0p = &QKV[(bb + k0 + 2 * kp) * QKV_N + hv + d8];
            uint4 v0 = *(const uint4*)v0p;
            uint4 v1 = *(const uint4*)(v0p + QKV_N);
            const ushort* a0 = (const ushort*)&v0;
            const ushort* a1 = (const ushort*)&v1;
#pragma unroll
            for (int i = 0; i < 8; i++)
                Vt[d8 + i][kp] = (uint32_t)a0[i] | ((uint32_t)a1[i] << 16);
        }
        __syncthreads();

        float s[8][4];
#pragma unroll
        for (int j = 0; j < 8; j++) {
            uint32_t kb[8];
            const uint32_t ab = kbase + (uint32_t)((8 * j + mr) * 36 + mi * 4) * 4;
            ldsm4(kb, ab);
            ldsm4(kb + 4, ab + 64);
            s[j][0] = s[j][1] = s[j][2] = s[j][3] = 0.f;
            mma_f16(s[j], qa[0], kb[0], kb[1]);
            mma_f16(s[j], qa[1], kb[2], kb[3]);
            mma_f16(s[j], qa[2], kb[4], kb[5]);
            mma_f16(s[j], qa[3], kb[6], kb[7]);
        }

        if (kt >= 2 * qt) {
            const int rg = qb + r0 + g;
#pragma unroll
            for (int j = 0; j < 8; j++) {
                const int col = k0 + 8 * j + 2 * t;
                if (col     > rg)     s[j][0] = -1e30f;
                if (col + 1 > rg)     s[j][1] = -1e30f;
                if (col     > rg + 8) s[j][2] = -1e30f;
                if (col + 1 > rg + 8) s[j][3] = -1e30f;
            }
        }

        float mg = -1e30f, mg8 = -1e30f;
#pragma unroll
        for (int j = 0; j < 8; j++) {
            mg  = fmaxf(mg,  fmaxf(s[j][0], s[j][1]));
            mg8 = fmaxf(mg8, fmaxf(s[j][2], s[j][3]));
        }
        mg  = fmaxf(mg,  __shfl_xor_sync(0xffffffffu, mg, 1));
        mg  = fmaxf(mg,  __shfl_xor_sync(0xffffffffu, mg, 2));
        mg8 = fmaxf(mg8, __shfl_xor_sync(0xffffffffu, mg8, 1));
        mg8 = fmaxf(mg8, __shfl_xor_sync(0xffffffffu, mg8, 2));
        const float mng  = fmaxf(m_g, mg);
        const float mng8 = fmaxf(m_g8, mg8);
        const float corr  = fast_ex2((m_g  - mng)  * SC);
        const float corr8 = fast_ex2((m_g8 - mng8) * SC);
        float sg = 0.f, sg8 = 0.f;
#pragma unroll
        for (int j = 0; j < 8; j++) {
            s[j][0] = fast_ex2((s[j][0] - mng)  * SC);
            s[j][1] = fast_ex2((s[j][1] - mng)  * SC);
            s[j][2] = fast_ex2((s[j][2] - mng8) * SC);
            s[j][3] = fast_ex2((s[j][3] - mng8) * SC);
            sg  += s[j][0] + s[j][1];
            sg8 += s[j][2] + s[j][3];
        }
        sg  += __shfl_xor_sync(0xffffffffu, sg, 1);
        sg  += __shfl_xor_sync(0xffffffffu, sg, 2);
        sg8 += __shfl_xor_sync(0xffffffffu, sg8, 1);
        sg8 += __shfl_xor_sync(0xffffffffu, sg8, 2);
        l_g  = l_g  * corr  + sg;
        l_g8 = l_g8 * corr8 + sg8;
        m_g = mng; m_g8 = mng8;
#pragma unroll
        for (int j = 0; j < 8; j++) {
            o[j][0] *= corr;  o[j][1] *= corr;
            o[j][2] *= corr8; o[j][3] *= corr8;
        }

        uint32_t pa[4][4];
#pragma unroll
        for (int km = 0; km < 4; km++) {
            pa[km][0] = f22h2(s[2 * km][0], s[2 * km][1]);
            pa[km][1] = f22h2(s[2 * km][2], s[2 * km][3]);
            pa[km][2] = f22h2(s[2 * km + 1][0], s[2 * km + 1][1]);
            pa[km][3] = f22h2(s[2 * km + 1][2], s[2 * km + 1][3]);
        }

#pragma unroll
        for (int j = 0; j < 8; j++) {
            uint32_t vb[8];
            const uint32_t ab = vbase + (uint32_t)((8 * j + mr) * 36 + mi * 4) * 4;
            ldsm4(vb, ab);
            ldsm4(vb + 4, ab + 64);
            mma_f16(o[j], pa[0], vb[0], vb[1]);
            mma_f16(o[j], pa[1], vb[2], vb[3]);
            mma_f16(o[j], pa[2], vb[4], vb[5]);
            mma_f16(o[j], pa[3], vb[6], vb[7]);
        }
        __syncthreads();
    }

    const float ig = 1.0f / l_g, ig8 = 1.0f / l_g8;
    __half* Og = Oh + (bb + qb + r0) * D_MODEL + hq;
#pragma unroll
    for (int j = 0; j < 8; j++) {
        const int col = 8 * j + 2 * t;
        *(__half2*)&Og[(size_t)g * D_MODEL + col] =
            __floats2half2_rn(o[j][0] * ig, o[j][1] * ig);
        *(__half2*)&Og[(size_t)(g + 8) * D_MODEL + col] =
            __floats2half2_rn(o[j][2] * ig8, o[j][3] * ig8);
    }
}

// ---------------- launch ----------------
extern "C" void kernel_launch(void* const* d_in, const int* in_sizes, int n_in,
                              void* d_out, int out_size)
{
    const float* x    = (const float*)d_in[0];
    const float* ln1s = (const float*)d_in[2];
    const float* ln1b = (const float*)d_in[3];
    const float* wq = (const float*)d_in[4];  const float* bq = (const float*)d_in[5];
    const float* wk = (const float*)d_in[6];  const float* bk = (const float*)d_in[7];
    const float* wv = (const float*)d_in[8];  const float* bv = (const float*)d_in[9];
    const float* wo = (const float*)d_in[10]; const float* bo = (const float*)d_in[11];
    const float* ln2s = (const float*)d_in[12];
    const float* ln2b = (const float*)d_in[13];
    const float* w1 = (const float*)d_in[14]; const float* b1 = (const float*)d_in[15];
    const float* w2 = (const float*)d_in[16]; const float* b2 = (const float*)d_in[17];
    float* out = (float*)d_out;

    __half *h1, *qkv, *att, *ff, *wqkvT, *woT, *w1T, *w2T;
    float *res, *bqkv;
    cudaGetSymbolAddress((void**)&h1,   g_h1);
    cudaGetSymbolAddress((void**)&qkv,  g_qkv);
    cudaGetSymbolAddress((void**)&att,  g_att);
    cudaGetSymbolAddress((void**)&res,  g_res);
    cudaGetSymbolAddress((void**)&ff,   g_ff);
    cudaGetSymbolAddress((void**)&wqkvT, g_wqkvT);
    cudaGetSymbolAddress((void**)&woT,  g_woT);
    cudaGetSymbolAddress((void**)&w1T,  g_w1T);
    cudaGetSymbolAddress((void**)&w2T,  g_w2T);
    cudaGetSymbolAddress((void**)&bqkv, g_bqkv);

    cudaFuncSetAttribute(gemm_h_kernel<1>, cudaFuncAttributeMaxDynamicSharedMemorySize, GEMM_SMEM);
    cudaFuncSetAttribute(gemm_h_kernel<2>, cudaFuncAttributeMaxDynamicSharedMemorySize, GEMM_SMEM);
    cudaFuncSetAttribute(gemm_h_kernel<3>, cudaFuncAttributeMaxDynamicSharedMemorySize, GEMM_SMEM);

    const dim3 tb(32, 8);
    transpose_h_kernel<<<dim3(D_MODEL / 32, D_MODEL / 32), tb>>>(wq, wqkvT, D_MODEL, D_MODEL);
    transpose_h_kernel<<<dim3(D_MODEL / 32, D_MODEL / 32), tb>>>(wk, wqkvT + (size_t)D_MODEL * D_MODEL, D_MODEL, D_MODEL);
    transpose_h_kernel<<<dim3(D_MODEL / 32, D_MODEL / 32), tb>>>(wv, wqkvT + (size_t)2 * D_MODEL * D_MODEL, D_MODEL, D_MODEL);
    transpose_h_kernel<<<dim3(D_MODEL / 32, D_MODEL / 32), tb>>>(wo, woT, D_MODEL, D_MODEL);
    transpose_h_kernel<<<dim3(DFF / 32, D_MODEL / 32), tb>>>(w1, w1T, D_MODEL, DFF);
    transpose_h_kernel<<<dim3(D_MODEL / 32, DFF / 32), tb>>>(w2, w2T, DFF, D_MODEL);
    bias_concat_kernel<<<QKV_N / 256, 256>>>(bq, bk, bv, bqkv);

    const dim3 gQKV(QKV_N / 128, MROWS / 128);   // (24, 64)
    const dim3 gD(D_MODEL / 128, MROWS / 128);   // (8, 64)
    const dim3 gF(DFF / 128,     MROWS / 128);   // (32, 64)

    ln_kernel<<<MROWS, 256>>>(x, ln1s, ln1b, h1);
    gemm_h_kernel<3><<<gQKV, 256, GEMM_SMEM>>>(h1, wqkvT, bqkv, nullptr, qkv, MROWS, QKV_N, D_MODEL);
    attn_tc_kernel<<<dim3(T_SEQ / 128, BATCH * NHEAD), 256>>>(qkv, att);
    gemm_h_kernel<1><<<gD, 256, GEMM_SMEM>>>(att, woT, bo, x, res, MROWS, D_MODEL, D_MODEL);
    ln_kernel<<<MROWS, 256>>>(res, ln2s, ln2b, h1);
    gemm_h_kernel<2><<<gF, 256, GEMM_SMEM>>>(h1, w1T, b1, nullptr, ff, MROWS, DFF, D_MODEL);
    gemm_h_kernel<1><<<gD, 256, GEMM_SMEM>>>(ff, w2T, b2, res, out, MROWS, D_MODEL, DFF);
}

// round 8
// speedup vs baseline: 1.0745x; 1.0263x over previous
#include <cuda_runtime.h>
#include <cuda_fp16.h>
#include <cstdint>
#include <cmath>

#define T_SEQ   1024
#define D_MODEL 1024
#define NHEAD   16
#define HDIM    64
#define DFF     4096
#define BATCH   8
#define MROWS   (BATCH * T_SEQ)
#define QKV_N   (3 * D_MODEL)

// ---------------- scratch (device globals: allocation-free) ----------------
__device__ __half g_h1 [(size_t)MROWS * D_MODEL];
__device__ __half g_qkv[(size_t)MROWS * QKV_N];
__device__ __half g_att[(size_t)MROWS * D_MODEL];
__device__ float  g_res[(size_t)MROWS * D_MODEL];
__device__ __half g_ff [(size_t)MROWS * DFF];
__device__ __half g_wqkvT[(size_t)QKV_N * D_MODEL];
__device__ __half g_woT[(size_t)D_MODEL * D_MODEL];
__device__ __half g_w1T[(size_t)DFF * D_MODEL];
__device__ __half g_w2T[(size_t)D_MODEL * DFF];
__device__ float  g_bqkv[QKV_N];

// ---------------- helpers ----------------
__device__ __forceinline__ uint32_t smem_u32(const void* p) {
    uint32_t a;
    asm("{ .reg .u64 t; cvta.to.shared.u64 t, %1; cvt.u32.u64 %0, t; }" : "=r"(a) : "l"(p));
    return a;
}
__device__ __forceinline__ float warp_sum(float v) {
#pragma unroll
    for (int o = 16; o > 0; o >>= 1) v += __shfl_xor_sync(0xffffffffu, v, o);
    return v;
}
__device__ __forceinline__ float fast_ex2(float x) {
    float y; asm("ex2.approx.f32 %0, %1;" : "=f"(y) : "f"(x)); return y;
}
__device__ __forceinline__ uint32_t h2ex2(uint32_t x) {
    uint32_t y; asm("ex2.approx.f16x2 %0, %1;" : "=r"(y) : "r"(x)); return y;
}
__device__ __forceinline__ float fast_tanh(float x) {
    float y; asm("tanh.approx.f32 %0, %1;" : "=f"(y) : "f"(x)); return y;
}
__device__ __forceinline__ float gelu_tanh(float x) {
    float x3 = x * x * x;
    float u  = 0.7978845608028654f * (x + 0.044715f * x3);
    return 0.5f * x * (1.0f + fast_tanh(u));
}
__device__ __forceinline__ void mma_f16(float* c, const uint32_t* a, uint32_t b0, uint32_t b1) {
    asm volatile(
        "mma.sync.aligned.m16n8k16.row.col.f32.f16.f16.f32 "
        "{%0,%1,%2,%3}, {%4,%5,%6,%7}, {%8,%9}, {%0,%1,%2,%3};\n"
        : "+f"(c[0]), "+f"(c[1]), "+f"(c[2]), "+f"(c[3])
        : "r"(a[0]), "r"(a[1]), "r"(a[2]), "r"(a[3]), "r"(b0), "r"(b1));
}
__device__ __forceinline__ void ldsm4(uint32_t* r, uint32_t addr) {
    asm volatile("ldmatrix.sync.aligned.m8n8.x4.shared.b16 {%0,%1,%2,%3}, [%4];"
        : "=r"(r[0]), "=r"(r[1]), "=r"(r[2]), "=r"(r[3]) : "r"(addr));
}
__device__ __forceinline__ uint32_t f22h2(float lo, float hi) {
    uint32_t u;
    asm("cvt.rn.f16x2.f32 %0, %1, %2;" : "=r"(u) : "f"(hi), "f"(lo));
    return u;
}
__device__ __forceinline__ void cp16(uint32_t dst, const void* src) {
    asm volatile("cp.async.cg.shared.global [%0], [%1], 16;" :: "r"(dst), "l"(src));
}
#define CP_COMMIT() asm volatile("cp.async.commit_group;" ::: "memory")
#define CP_WAIT1()  asm volatile("cp.async.wait_group 1;" ::: "memory")
#define CP_WAIT0()  asm volatile("cp.async.wait_group 0;" ::: "memory")

// ---------------- weight transpose -> half: out[C][R] = (half)in[R][C] ----
__global__ __launch_bounds__(256) void transpose_h_kernel(
    const float* __restrict__ in, __half* __restrict__ out, int R, int C)
{
    __shared__ float t[32][33];
    const int bx = blockIdx.x * 32, by = blockIdx.y * 32;
    const int tx = threadIdx.x, ty = threadIdx.y;  // (32, 8)
#pragma unroll
    for (int i = 0; i < 4; i++)
        t[ty + 8 * i][tx] = in[(size_t)(by + ty + 8 * i) * C + bx + tx];
    __syncthreads();
#pragma unroll
    for (int i = 0; i < 4; i++)
        out[(size_t)(bx + ty + 8 * i) * R + by + tx] = __float2half_rn(t[tx][ty + 8 * i]);
}

__global__ void bias_concat_kernel(const float* __restrict__ bq,
                                   const float* __restrict__ bk,
                                   const float* __restrict__ bv,
                                   float* __restrict__ o)
{
    const int i = blockIdx.x * 256 + threadIdx.x;
    o[i] = (i < D_MODEL) ? bq[i] : (i < 2 * D_MODEL) ? bk[i - D_MODEL] : bv[i - 2 * D_MODEL];
}

// ---------------- LayerNorm (f32 in -> half out) ----------------
__global__ __launch_bounds__(256) void ln_kernel(
    const float* __restrict__ x, const float* __restrict__ sc,
    const float* __restrict__ bi, __half* __restrict__ y)
{
    __shared__ float redm[8], redv[8], bcast[2];
    const int row = blockIdx.x, tid = threadIdx.x;
    const int wid = tid >> 5, lane = tid & 31;

    float4 v = *(const float4*)&x[(size_t)row * D_MODEL + tid * 4];
    float s = warp_sum(v.x + v.y + v.z + v.w);
    if (lane == 0) redm[wid] = s;
    __syncthreads();
    if (tid == 0) {
        float tot = 0.f;
#pragma unroll
        for (int i = 0; i < 8; i++) tot += redm[i];
        bcast[0] = tot * (1.0f / 1024.0f);
    }
    __syncthreads();
    const float mean = bcast[0];
    float dx = v.x - mean, dy = v.y - mean, dz = v.z - mean, dw = v.w - mean;
    float ss = warp_sum(dx * dx + dy * dy + dz * dz + dw * dw);
    if (lane == 0) redv[wid] = ss;
    __syncthreads();
    if (tid == 0) {
        float tot = 0.f;
#pragma unroll
        for (int i = 0; i < 8; i++) tot += redv[i];
        bcast[1] = rsqrtf(tot * (1.0f / 1024.0f) + 1e-6f);
    }
    __syncthreads();
    const float rstd = bcast[1];
    float4 scv = *(const float4*)&sc[tid * 4];
    float4 biv = *(const float4*)&bi[tid * 4];
    __half2* yp = (__half2*)&y[(size_t)row * D_MODEL + tid * 4];
    yp[0] = __floats2half2_rn(dx * rstd * scv.x + biv.x, dy * rstd * scv.y + biv.y);
    yp[1] = __floats2half2_rn(dz * rstd * scv.z + biv.z, dw * rstd * scv.w + biv.w);
}

// ---------------- fp16 GEMM, 128x128 CTA, 2-stage cp.async (R5 config) ----
// C = A[M,K] @ Bt[N,K]^T + bias; EPI: 1 = f32 +res, 2 = half gelu, 3 = half
#define HSTG 4608  // uint32 per operand stage
#define GEMM_SMEM (4 * HSTG * 4)  // 73728 bytes

template <int EPI>
__global__ __launch_bounds__(256, 2) void gemm_h_kernel(
    const __half* __restrict__ A, const __half* __restrict__ Bt,
    const float* __restrict__ bias, const float* __restrict__ res,
    void* __restrict__ Cv, int M, int N, int K)
{
    extern __shared__ uint32_t smh[];
    const uint32_t smb = smem_u32(smh);
    const int tid = threadIdx.x;
    const int wid = tid >> 5, lane = tid & 31;
    const int g = lane >> 2, t = lane & 3;
    const int mi = lane >> 3, mr = lane & 7;
    const int rowoff = (mi & 1) * 8, koff = (mi >> 1) * 4;  // uint32 units
    const int warpM = (wid >> 2) * 64, warpN = (wid & 3) * 32;
    const int bm = blockIdx.y * 128, bn = blockIdx.x * 128;
    const int nch = K >> 6;

    const __half* Ab = A + (size_t)bm * K;
    const __half* Bb = Bt + (size_t)bn * K;

    // preload chunk 0 into stage 0
    {
#pragma unroll
        for (int r = 0; r < 4; r++) {
            const int idx = tid + 256 * r;
            const int row = idx >> 3, p = idx & 7;
            const uint32_t da = smb + (uint32_t)(row * 36 + p * 4) * 4;
            const uint32_t db = smb + (uint32_t)(2 * HSTG + row * 36 + p * 4) * 4;
            cp16(da, Ab + (size_t)row * K + p * 8);
            cp16(db, Bb + (size_t)row * K + p * 8);
        }
        CP_COMMIT();
    }

    float c[4][4][4];
#pragma unroll
    for (int i = 0; i < 4; i++)
#pragma unroll
        for (int j = 0; j < 4; j++)
#pragma unroll
            for (int q = 0; q < 4; q++) c[i][j][q] = 0.f;

    for (int ch = 0; ch < nch; ch++) {
        const int s = ch & 1;
        if (ch + 1 < nch) {
            const int k0 = (ch + 1) << 6;
#pragma unroll
            for (int r = 0; r < 4; r++) {
                const int idx = tid + 256 * r;
                const int row = idx >> 3, p = idx & 7;
                const uint32_t da = smb + (uint32_t)((s ^ 1) * HSTG + row * 36 + p * 4) * 4;
                const uint32_t db = smb + (uint32_t)((2 + (s ^ 1)) * HSTG + row * 36 + p * 4) * 4;
                cp16(da, Ab + (size_t)row * K + k0 + p * 8);
                cp16(db, Bb + (size_t)row * K + k0 + p * 8);
            }
            CP_COMMIT();
            CP_WAIT1();
        } else {
            CP_WAIT0();
        }
        __syncthreads();

        const uint32_t Ast = smb + (uint32_t)(s * HSTG) * 4;
        const uint32_t Bst = smb + (uint32_t)((2 + s) * HSTG) * 4;

        uint32_t bf[4][8];
#pragma unroll
        for (int j = 0; j < 4; j++) {
            const uint32_t ab = Bst + (uint32_t)((warpN + 8 * j + mr) * 36 + mi * 4) * 4;
            ldsm4(bf[j], ab);
            ldsm4(bf[j] + 4, ab + 64);
        }
#pragma unroll
        for (int i = 0; i < 4; i++) {
            uint32_t af[4][4];
            const uint32_t aa = Ast + (uint32_t)((warpM + 16 * i + rowoff + mr) * 36 + koff) * 4;
#pragma unroll
            for (int km = 0; km < 4; km++) ldsm4(af[km], aa + km * 32u);
#pragma unroll
            for (int j = 0; j < 4; j++) {
                mma_f16(c[i][j], af[0], bf[j][0], bf[j][1]);
                mma_f16(c[i][j], af[1], bf[j][2], bf[j][3]);
                mma_f16(c[i][j], af[2], bf[j][4], bf[j][5]);
                mma_f16(c[i][j], af[3], bf[j][6], bf[j][7]);
            }
        }
        __syncthreads();
    }

    // epilogue
#pragma unroll
    for (int i = 0; i < 4; i++) {
#pragma unroll
        for (int j = 0; j < 4; j++) {
            const int row0 = bm + warpM + 16 * i + g;
            const int col  = bn + warpN + 8 * j + 2 * t;
            const float b0 = bias[col], b1 = bias[col + 1];
            float v00 = c[i][j][0] + b0, v01 = c[i][j][1] + b1;
            float v10 = c[i][j][2] + b0, v11 = c[i][j][3] + b1;
            if (EPI == 1) {
                float* C = (float*)Cv;
                float2 r0 = *(const float2*)&res[(size_t)row0 * N + col];
                float2 r1 = *(const float2*)&res[(size_t)(row0 + 8) * N + col];
                *(float2*)&C[(size_t)row0 * N + col]       = make_float2(v00 + r0.x, v01 + r0.y);
                *(float2*)&C[(size_t)(row0 + 8) * N + col] = make_float2(v10 + r1.x, v11 + r1.y);
            } else if (EPI == 2) {
                __half* C = (__half*)Cv;
                *(__half2*)&C[(size_t)row0 * N + col] =
                    __floats2half2_rn(gelu_tanh(v00), gelu_tanh(v01));
                *(__half2*)&C[(size_t)(row0 + 8) * N + col] =
                    __floats2half2_rn(gelu_tanh(v10), gelu_tanh(v11));
            } else {  // EPI == 3
                __half* C = (__half*)Cv;
                *(__half2*)&C[(size_t)row0 * N + col]       = __floats2half2_rn(v00, v01);
                *(__half2*)&C[(size_t)(row0 + 8) * N + col] = __floats2half2_rn(v10, v11);
            }
        }
    }
}

// ---------------- tensor-core causal flash attention (fp16 mma, fp32 accum) ----
// softmax probabilities via ex2.approx.f16x2 (half the MUFU ops; P was f16 anyway)
__global__ __launch_bounds__(256, 2) void attn_tc_kernel(
    const __half* __restrict__ QKV, __half* __restrict__ Oh)
{
    __shared__ uint32_t Qs[128][36];
    __shared__ uint32_t Ks[64][36];
    __shared__ uint32_t Vt[64][36];

    const int qt  = (int)gridDim.x - 1 - (int)blockIdx.x;
    const int bh  = blockIdx.y;
    const int b   = bh >> 4, h = bh & 15;
    const int tid = threadIdx.x, wid = tid >> 5, lane = tid & 31;
    const int g = lane >> 2, t = lane & 3;
    const int qb = qt * 128;
    const size_t bb = (size_t)b * T_SEQ;
    const int hq = h * HDIM, hk = hq + D_MODEL, hv = hq + 2 * D_MODEL;
    const int r0 = wid * 16;

#pragma unroll
    for (int r = 0; r < 4; r++) {
        const int lin = tid + 256 * r;
        const int row = lin >> 3, c = lin & 7;
        *(uint4*)&Qs[row][4 * c] =
            *(const uint4*)&QKV[(bb + qb + row) * QKV_N + hq + 8 * c];
    }
    __syncthreads();

    uint32_t qa[4][4];
    {
        const uint32_t qbase = smem_u32(Qs);
        const int mi = lane >> 3, mr = lane & 7;
        const int rowoff = (mi & 1) * 8, koff = (mi >> 1) * 4;
#pragma unroll
        for (int km = 0; km < 4; km++)
            ldsm4(qa[km], qbase + (uint32_t)((r0 + rowoff + mr) * 36 + km * 8 + koff) * 4);
    }

    float o[8][4];
#pragma unroll
    for (int j = 0; j < 8; j++)
#pragma unroll
        for (int q = 0; q < 4; q++) o[j][q] = 0.f;
    float m_g = -1e30f, m_g8 = -1e30f, l_g = 0.f, l_g8 = 0.f;
    const float SC = 0.18033688011112042f;  // (1/8) * log2(e)

    const uint32_t kbase = smem_u32(Ks), vbase = smem_u32(Vt);
    const int mi = lane >> 3, mr = lane & 7;

    const int nkt = 2 * qt + 2;
    for (int kt = 0; kt < nkt; kt++) {
        const int k0 = kt * 64;
#pragma unroll
        for (int r = 0; r < 2; r++) {
            const int lin = tid + 256 * r;
            const int row = lin >> 3, c = lin & 7;
            *(uint4*)&Ks[row][4 * c] =
                *(const uint4*)&QKV[(bb + k0 + row) * QKV_N + hk + 8 * c];
        }
        {
            const int kp = tid & 31, d8 = (tid >> 5) * 8;
            const __half* v0p = &QKV[(bb + k0 + 2 * kp) * QKV_N + hv + d8];
            uint4 v0 = *(const uint4*)v0p;
            uint4 v1 = *(const uint4*)(v0p + QKV_N);
            const ushort* a0 = (const ushort*)&v0;
            const ushort* a1 = (const ushort*)&v1;
#pragma unroll
            for (int i = 0; i < 8; i++)
                Vt[d8 + i][kp] = (uint32_t)a0[i] | ((uint32_t)a1[i] << 16);
        }
        __syncthreads();

        float s[8][4];
#pragma unroll
        for (int j = 0; j < 8; j++) {
            uint32_t kb[8];
            const uint32_t ab = kbase + (uint32_t)((8 * j + mr) * 36 + mi * 4) * 4;
            ldsm4(kb, ab);
            ldsm4(kb + 4, ab + 64);
            s[j][0] = s[j][1] = s[j][2] = s[j][3] = 0.f;
            mma_f16(s[j], qa[0], kb[0], kb[1]);
            mma_f16(s[j], qa[1], kb[2], kb[3]);
            mma_f16(s[j], qa[2], kb[4], kb[5]);
            mma_f16(s[j], qa[3], kb[6], kb[7]);
        }

        if (kt >= 2 * qt) {
            const int rg = qb + r0 + g;
#pragma unroll
            for (int j = 0; j < 8; j++) {
                const int col = k0 + 8 * j + 2 * t;
                if (col     > rg)     s[j][0] = -1e30f;
                if (col + 1 > rg)     s[j][1] = -1e30f;
                if (col     > rg + 8) s[j][2] = -1e30f;
                if (col + 1 > rg + 8) s[j][3] = -1e30f;
            }
        }

        // running max (f32)
        float mg = -1e30f, mg8 = -1e30f;
#pragma unroll
        for (int j = 0; j < 8; j++) {
            mg  = fmaxf(mg,  fmaxf(s[j][0], s[j][1]));
            mg8 = fmaxf(mg8, fmaxf(s[j][2], s[j][3]));
        }
        mg  = fmaxf(mg,  __shfl_xor_sync(0xffffffffu, mg, 1));
        mg  = fmaxf(mg,  __shfl_xor_sync(0xffffffffu, mg, 2));
        mg8 = fmaxf(mg8, __shfl_xor_sync(0xffffffffu, mg8, 1));
        mg8 = fmaxf(mg8, __shfl_xor_sync(0xffffffffu, mg8, 2));
        const float mng  = fmaxf(m_g, mg);
        const float mng8 = fmaxf(m_g8, mg8);
        const float corr  = fast_ex2((m_g  - mng)  * SC);
        const float corr8 = fast_ex2((m_g8 - mng8) * SC);
        const float c1 = mng * SC, c2 = mng8 * SC;

        // P = 2^((s-m)*SC) computed directly in f16x2; result IS the mma a-frag
        uint32_t pa[4][4];
        float sg = 0.f, sg8 = 0.f;
#pragma unroll
        for (int km = 0; km < 4; km++) {
#pragma unroll
            for (int jj = 0; jj < 2; jj++) {
                const int j = 2 * km + jj;
                uint32_t p01 = h2ex2(f22h2(s[j][0] * SC - c1, s[j][1] * SC - c1));
                uint32_t p23 = h2ex2(f22h2(s[j][2] * SC - c2, s[j][3] * SC - c2));
                pa[km][2 * jj]     = p01;
                pa[km][2 * jj + 1] = p23;
                float2 f01 = __half22float2(*(__half2*)&p01);
                float2 f23 = __half22float2(*(__half2*)&p23);
                sg  += f01.x + f01.y;
                sg8 += f23.x + f23.y;
            }
        }
        sg  += __shfl_xor_sync(0xffffffffu, sg, 1);
        sg  += __shfl_xor_sync(0xffffffffu, sg, 2);
        sg8 += __shfl_xor_sync(0xffffffffu, sg8, 1);
        sg8 += __shfl_xor_sync(0xffffffffu, sg8, 2);
        l_g  = l_g  * corr  + sg;
        l_g8 = l_g8 * corr8 + sg8;
        m_g = mng; m_g8 = mng8;
#pragma unroll
        for (int j = 0; j < 8; j++) {
            o[j][0] *= corr;  o[j][1] *= corr;
            o[j][2] *= corr8; o[j][3] *= corr8;
        }

#pragma unroll
        for (int j = 0; j < 8; j++) {
            uint32_t vb[8];
            const uint32_t ab = vbase + (uint32_t)((8 * j + mr) * 36 + mi * 4) * 4;
            ldsm4(vb, ab);
            ldsm4(vb + 4, ab + 64);
            mma_f16(o[j], pa[0], vb[0], vb[1]);
            mma_f16(o[j], pa[1], vb[2], vb[3]);
            mma_f16(o[j], pa[2], vb[4], vb[5]);
            mma_f16(o[j], pa[3], vb[6], vb[7]);
        }
        __syncthreads();
    }

    const float ig = 1.0f / l_g, ig8 = 1.0f / l_g8;
    __half* Og = Oh + (bb + qb + r0) * D_MODEL + hq;
#pragma unroll
    for (int j = 0; j < 8; j++) {
        const int col = 8 * j + 2 * t;
        *(__half2*)&Og[(size_t)g * D_MODEL + col] =
            __floats2half2_rn(o[j][0] * ig, o[j][1] * ig);
        *(__half2*)&Og[(size_t)(g + 8) * D_MODEL + col] =
            __floats2half2_rn(o[j][2] * ig8, o[j][3] * ig8);
    }
}

// ---------------- launch ----------------
// Order matters for ncu (-s 5 -c 1 captures the 6th launch = QKV GEMM).
extern "C" void kernel_launch(void* const* d_in, const int* in_sizes, int n_in,
                              void* d_out, int out_size)
{
    const float* x    = (const float*)d_in[0];
    const float* ln1s = (const float*)d_in[2];
    const float* ln1b = (const float*)d_in[3];
    const float* wq = (const float*)d_in[4];  const float* bq = (const float*)d_in[5];
    const float* wk = (const float*)d_in[6];  const float* bk = (const float*)d_in[7];
    const float* wv = (const float*)d_in[8];  const float* bv = (const float*)d_in[9];
    const float* wo = (const float*)d_in[10]; const float* bo = (const float*)d_in[11];
    const float* ln2s = (const float*)d_in[12];
    const float* ln2b = (const float*)d_in[13];
    const float* w1 = (const float*)d_in[14]; const float* b1 = (const float*)d_in[15];
    const float* w2 = (const float*)d_in[16]; const float* b2 = (const float*)d_in[17];
    float* out = (float*)d_out;

    __half *h1, *qkv, *att, *ff, *wqkvT, *woT, *w1T, *w2T;
    float *res, *bqkv;
    cudaGetSymbolAddress((void**)&h1,   g_h1);
    cudaGetSymbolAddress((void**)&qkv,  g_qkv);
    cudaGetSymbolAddress((void**)&att,  g_att);
    cudaGetSymbolAddress((void**)&res,  g_res);
    cudaGetSymbolAddress((void**)&ff,   g_ff);
    cudaGetSymbolAddress((void**)&wqkvT, g_wqkvT);
    cudaGetSymbolAddress((void**)&woT,  g_woT);
    cudaGetSymbolAddress((void**)&w1T,  g_w1T);
    cudaGetSymbolAddress((void**)&w2T,  g_w2T);
    cudaGetSymbolAddress((void**)&bqkv, g_bqkv);

    cudaFuncSetAttribute(gemm_h_kernel<1>, cudaFuncAttributeMaxDynamicSharedMemorySize, GEMM_SMEM);
    cudaFuncSetAttribute(gemm_h_kernel<2>, cudaFuncAttributeMaxDynamicSharedMemorySize, GEMM_SMEM);
    cudaFuncSetAttribute(gemm_h_kernel<3>, cudaFuncAttributeMaxDynamicSharedMemorySize, GEMM_SMEM);

    const dim3 tb(32, 8);
    const dim3 gQKV(QKV_N / 128, MROWS / 128);   // (24, 64)
    const dim3 gD(D_MODEL / 128, MROWS / 128);   // (8, 64)
    const dim3 gF(DFF / 128,     MROWS / 128);   // (32, 64)

    // launches 1-5
    transpose_h_kernel<<<dim3(D_MODEL / 32, D_MODEL / 32), tb>>>(wq, wqkvT, D_MODEL, D_MODEL);
    transpose_h_kernel<<<dim3(D_MODEL / 32, D_MODEL / 32), tb>>>(wk, wqkvT + (size_t)D_MODEL * D_MODEL, D_MODEL, D_MODEL);
    transpose_h_kernel<<<dim3(D_MODEL / 32, D_MODEL / 32), tb>>>(wv, wqkvT + (size_t)2 * D_MODEL * D_MODEL, D_MODEL, D_MODEL);
    bias_concat_kernel<<<QKV_N / 256, 256>>>(bq, bk, bv, bqkv);
    ln_kernel<<<MROWS, 256>>>(x, ln1s, ln1b, h1);
    // launch 6 (ncu captures this one): the QKV GEMM
    gemm_h_kernel<3><<<gQKV, 256, GEMM_SMEM>>>(h1, wqkvT, bqkv, nullptr, qkv, MROWS, QKV_N, D_MODEL);
    // remaining transposes (needed before their GEMMs)
    transpose_h_kernel<<<dim3(D_MODEL / 32, D_MODEL / 32), tb>>>(wo, woT, D_MODEL, D_MODEL);
    transpose_h_kernel<<<dim3(DFF / 32, D_MODEL / 32), tb>>>(w1, w1T, D_MODEL, DFF);
    transpose_h_kernel<<<dim3(D_MODEL / 32, DFF / 32), tb>>>(w2, w2T, DFF, D_MODEL);
    attn_tc_kernel<<<dim3(T_SEQ / 128, BATCH * NHEAD), 256>>>(qkv, att);
    gemm_h_kernel<1><<<gD, 256, GEMM_SMEM>>>(att, woT, bo, x, res, MROWS, D_MODEL, D_MODEL);
    ln_kernel<<<MROWS, 256>>>(res, ln2s, ln2b, h1);
    gemm_h_kernel<2><<<gF, 256, GEMM_SMEM>>>(h1, w1T, b1, nullptr, ff, MROWS, DFF, D_MODEL);
    gemm_h_kernel<1><<<gD, 256, GEMM_SMEM>>>(ff, w2T, b2, res, out, MROWS, D_MODEL, DFF);
}

// round 9
// speedup vs baseline: 1.1016x; 1.0252x over previous
#include <cuda_runtime.h>
#include <cuda_fp16.h>
#include <cstdint>
#include <cmath>

#define T_SEQ   1024
#define D_MODEL 1024
#define NHEAD   16
#define HDIM    64
#define DFF     4096
#define BATCH   8
#define MROWS   (BATCH * T_SEQ)
#define QKV_N   (3 * D_MODEL)

// ---------------- scratch (device globals: allocation-free) ----------------
__device__ __half g_h1 [(size_t)MROWS * D_MODEL];
__device__ __half g_qkv[(size_t)MROWS * QKV_N];
__device__ __half g_att[(size_t)MROWS * D_MODEL];
__device__ float  g_res[(size_t)MROWS * D_MODEL];
__device__ __half g_ff [(size_t)MROWS * DFF];
__device__ __half g_wqkvT[(size_t)QKV_N * D_MODEL];
__device__ __half g_woT[(size_t)D_MODEL * D_MODEL];
__device__ __half g_w1T[(size_t)DFF * D_MODEL];
__device__ __half g_w2T[(size_t)D_MODEL * DFF];

// ---------------- helpers ----------------
__device__ __forceinline__ uint32_t smem_u32(const void* p) {
    uint32_t a;
    asm("{ .reg .u64 t; cvta.to.shared.u64 t, %1; cvt.u32.u64 %0, t; }" : "=r"(a) : "l"(p));
    return a;
}
__device__ __forceinline__ float warp_sum(float v) {
#pragma unroll
    for (int o = 16; o > 0; o >>= 1) v += __shfl_xor_sync(0xffffffffu, v, o);
    return v;
}
__device__ __forceinline__ float fast_ex2(float x) {
    float y; asm("ex2.approx.f32 %0, %1;" : "=f"(y) : "f"(x)); return y;
}
__device__ __forceinline__ uint32_t h2ex2(uint32_t x) {
    uint32_t y; asm("ex2.approx.f16x2 %0, %1;" : "=r"(y) : "r"(x)); return y;
}
__device__ __forceinline__ float fast_tanh(float x) {
    float y; asm("tanh.approx.f32 %0, %1;" : "=f"(y) : "f"(x)); return y;
}
__device__ __forceinline__ float gelu_tanh(float x) {
    float x3 = x * x * x;
    float u  = 0.7978845608028654f * (x + 0.044715f * x3);
    return 0.5f * x * (1.0f + fast_tanh(u));
}
__device__ __forceinline__ void mma_f16(float* c, const uint32_t* a, uint32_t b0, uint32_t b1) {
    asm volatile(
        "mma.sync.aligned.m16n8k16.row.col.f32.f16.f16.f32 "
        "{%0,%1,%2,%3}, {%4,%5,%6,%7}, {%8,%9}, {%0,%1,%2,%3};\n"
        : "+f"(c[0]), "+f"(c[1]), "+f"(c[2]), "+f"(c[3])
        : "r"(a[0]), "r"(a[1]), "r"(a[2]), "r"(a[3]), "r"(b0), "r"(b1));
}
__device__ __forceinline__ void ldsm4(uint32_t* r, uint32_t addr) {
    asm volatile("ldmatrix.sync.aligned.m8n8.x4.shared.b16 {%0,%1,%2,%3}, [%4];"
        : "=r"(r[0]), "=r"(r[1]), "=r"(r[2]), "=r"(r[3]) : "r"(addr));
}
__device__ __forceinline__ uint32_t f22h2(float lo, float hi) {
    uint32_t u;
    asm("cvt.rn.f16x2.f32 %0, %1, %2;" : "=r"(u) : "f"(hi), "f"(lo));
    return u;
}
__device__ __forceinline__ void cp16(uint32_t dst, const void* src) {
    asm volatile("cp.async.cg.shared.global [%0], [%1], 16;" :: "r"(dst), "l"(src));
}
#define CP_COMMIT() asm volatile("cp.async.commit_group;" ::: "memory")
#define CP_WAIT0()  asm volatile("cp.async.wait_group 0;" ::: "memory")

// ---------------- weight transpose -> half: out[C][R] = (half)in[R][C] ----
__global__ __launch_bounds__(256) void transpose_h_kernel(
    const float* __restrict__ in, __half* __restrict__ out, int R, int C)
{
    __shared__ float t[32][33];
    const int bx = blockIdx.x * 32, by = blockIdx.y * 32;
    const int tx = threadIdx.x, ty = threadIdx.y;  // (32, 8)
#pragma unroll
    for (int i = 0; i < 4; i++)
        t[ty + 8 * i][tx] = in[(size_t)(by + ty + 8 * i) * C + bx + tx];
    __syncthreads();
#pragma unroll
    for (int i = 0; i < 4; i++)
        out[(size_t)(bx + ty + 8 * i) * R + by + tx] = __float2half_rn(t[tx][ty + 8 * i]);
}

// ---------------- LayerNorm (single-pass sum/sumsq; f32 in -> half out) ----
__global__ __launch_bounds__(256) void ln_kernel(
    const float* __restrict__ x, const float* __restrict__ sc,
    const float* __restrict__ bi, __half* __restrict__ y)
{
    __shared__ float reds[8], redq[8], bcast[2];
    const int row = blockIdx.x, tid = threadIdx.x;
    const int wid = tid >> 5, lane = tid & 31;

    float4 v = *(const float4*)&x[(size_t)row * D_MODEL + tid * 4];
    float s = v.x + v.y + v.z + v.w;
    float q = v.x * v.x + v.y * v.y + v.z * v.z + v.w * v.w;
    s = warp_sum(s);
    q = warp_sum(q);
    if (lane == 0) { reds[wid] = s; redq[wid] = q; }
    __syncthreads();
    if (tid == 0) {
        float ts = 0.f, tq = 0.f;
#pragma unroll
        for (int i = 0; i < 8; i++) { ts += reds[i]; tq += redq[i]; }
        const float mean = ts * (1.0f / 1024.0f);
        bcast[0] = mean;
        bcast[1] = rsqrtf(tq * (1.0f / 1024.0f) - mean * mean + 1e-6f);
    }
    __syncthreads();
    const float mean = bcast[0], rstd = bcast[1];
    float4 scv = *(const float4*)&sc[tid * 4];
    float4 biv = *(const float4*)&bi[tid * 4];
    __half2* yp = (__half2*)&y[(size_t)row * D_MODEL + tid * 4];
    yp[0] = __floats2half2_rn((v.x - mean) * rstd * scv.x + biv.x,
                              (v.y - mean) * rstd * scv.y + biv.y);
    yp[1] = __floats2half2_rn((v.z - mean) * rstd * scv.z + biv.z,
                              (v.w - mean) * rstd * scv.w + biv.w);
}

// ---------------- fp16 GEMM, 128x128 CTA, 2-stage cp.async, 1 sync/chunk ----
// C = A[M,K] @ Bt[N,K]^T + bias; EPI: 1 = f32 +res, 2 = half gelu, 3 = half qkv
// EPI 3: bias selected per 1024-col segment from {bias, bias2, bias3}.
#define HSTG 4608  // uint32 per operand stage
#define GEMM_SMEM (4 * HSTG * 4)  // 73728 bytes

template <int EPI>
__global__ __launch_bounds__(256, 2) void gemm_h_kernel(
    const __half* __restrict__ A, const __half* __restrict__ Bt,
    const float* __restrict__ bias, const float* __restrict__ bias2,
    const float* __restrict__ bias3, const float* __restrict__ res,
    void* __restrict__ Cv, int M, int N, int K)
{
    extern __shared__ uint32_t smh[];
    const uint32_t smb = smem_u32(smh);
    const int tid = threadIdx.x;
    const int wid = tid >> 5, lane = tid & 31;
    const int g = lane >> 2, t = lane & 3;
    const int mi = lane >> 3, mr = lane & 7;
    const int rowoff = (mi & 1) * 8, koff = (mi >> 1) * 4;  // uint32 units
    const int warpM = (wid >> 2) * 64, warpN = (wid & 3) * 32;
    const int bm = blockIdx.y * 128, bn = blockIdx.x * 128;
    const int nch = K >> 6;

    const __half* Ab = A + (size_t)bm * K;
    const __half* Bb = Bt + (size_t)bn * K;

    // QKV bias segment select (whole CTA lies in one 1024-col segment)
    const float* biasSeg = bias;
    int colShift = 0;
    if (EPI == 3) {
        const int seg = bn >> 10;
        biasSeg = (seg == 0) ? bias : (seg == 1) ? bias2 : bias3;
        colShift = seg << 10;
    }

    // fill chunk into stage st
    auto fill = [&](int st, int k0) {
#pragma unroll
        for (int r = 0; r < 4; r++) {
            const int idx = tid + 256 * r;
            const int row = idx >> 3, p = idx & 7;
            const uint32_t da = smb + (uint32_t)(st * HSTG + row * 36 + p * 4) * 4;
            const uint32_t db = smb + (uint32_t)((2 + st) * HSTG + row * 36 + p * 4) * 4;
            cp16(da, Ab + (size_t)row * K + k0 + p * 8);
            cp16(db, Bb + (size_t)row * K + k0 + p * 8);
        }
        CP_COMMIT();
    };

    fill(0, 0);

    float c[4][4][4];
#pragma unroll
    for (int i = 0; i < 4; i++)
#pragma unroll
        for (int j = 0; j < 4; j++)
#pragma unroll
            for (int q = 0; q < 4; q++) c[i][j][q] = 0.f;

    for (int ch = 0; ch < nch; ch++) {
        const int s = ch & 1;
        CP_WAIT0();            // chunk ch resident in stage s
        __syncthreads();       // all warps done reading stage s^1 AND see chunk ch
        if (ch + 1 < nch) fill(s ^ 1, (ch + 1) << 6);  // overlaps compute below

        const uint32_t Ast = smb + (uint32_t)(s * HSTG) * 4;
        const uint32_t Bst = smb + (uint32_t)((2 + s) * HSTG) * 4;

        uint32_t bf[4][8];
#pragma unroll
        for (int j = 0; j < 4; j++) {
            const uint32_t ab = Bst + (uint32_t)((warpN + 8 * j + mr) * 36 + mi * 4) * 4;
            ldsm4(bf[j], ab);
            ldsm4(bf[j] + 4, ab + 64);
        }
#pragma unroll
        for (int i = 0; i < 4; i++) {
            uint32_t af[4][4];
            const uint32_t aa = Ast + (uint32_t)((warpM + 16 * i + rowoff + mr) * 36 + koff) * 4;
#pragma unroll
            for (int km = 0; km < 4; km++) ldsm4(af[km], aa + km * 32u);
#pragma unroll
            for (int j = 0; j < 4; j++) {
                mma_f16(c[i][j], af[0], bf[j][0], bf[j][1]);
                mma_f16(c[i][j], af[1], bf[j][2], bf[j][3]);
                mma_f16(c[i][j], af[2], bf[j][4], bf[j][5]);
                mma_f16(c[i][j], af[3], bf[j][6], bf[j][7]);
            }
        }
    }

    // epilogue
#pragma unroll
    for (int i = 0; i < 4; i++) {
#pragma unroll
        for (int j = 0; j < 4; j++) {
            const int row0 = bm + warpM + 16 * i + g;
            const int col  = bn + warpN + 8 * j + 2 * t;
            const int bcol = (EPI == 3) ? (col - colShift) : col;
            const float b0 = biasSeg[bcol], b1 = biasSeg[bcol + 1];
            float v00 = c[i][j][0] + b0, v01 = c[i][j][1] + b1;
            float v10 = c[i][j][2] + b0, v11 = c[i][j][3] + b1;
            if (EPI == 1) {
                float* C = (float*)Cv;
                float2 r0 = *(const float2*)&res[(size_t)row0 * N + col];
                float2 r1 = *(const float2*)&res[(size_t)(row0 + 8) * N + col];
                *(float2*)&C[(size_t)row0 * N + col]       = make_float2(v00 + r0.x, v01 + r0.y);
                *(float2*)&C[(size_t)(row0 + 8) * N + col] = make_float2(v10 + r1.x, v11 + r1.y);
            } else if (EPI == 2) {
                __half* C = (__half*)Cv;
                *(__half2*)&C[(size_t)row0 * N + col] =
                    __floats2half2_rn(gelu_tanh(v00), gelu_tanh(v01));
                *(__half2*)&C[(size_t)(row0 + 8) * N + col] =
                    __floats2half2_rn(gelu_tanh(v10), gelu_tanh(v11));
            } else {  // EPI == 3
                __half* C = (__half*)Cv;
                *(__half2*)&C[(size_t)row0 * N + col]       = __floats2half2_rn(v00, v01);
                *(__half2*)&C[(size_t)(row0 + 8) * N + col] = __floats2half2_rn(v10, v11);
            }
        }
    }
}

// ---------------- tensor-core causal flash attention (fp16 mma, fp32 accum) ----
__global__ __launch_bounds__(256, 2) void attn_tc_kernel(
    const __half* __restrict__ QKV, __half* __restrict__ Oh)
{
    __shared__ uint32_t Qs[128][36];
    __shared__ uint32_t Ks[64][36];
    __shared__ uint32_t Vt[64][36];

    const int qt  = (int)gridDim.x - 1 - (int)blockIdx.x;
    const int bh  = blockIdx.y;
    const int b   = bh >> 4, h = bh & 15;
    const int tid = threadIdx.x, wid = tid >> 5, lane = tid & 31;
    const int g = lane >> 2, t = lane & 3;
    const int qb = qt * 128;
    const size_t bb = (size_t)b * T_SEQ;
    const int hq = h * HDIM, hk = hq + D_MODEL, hv = hq + 2 * D_MODEL;
    const int r0 = wid * 16;

#pragma unroll
    for (int r = 0; r < 4; r++) {
        const int lin = tid + 256 * r;
        const int row = lin >> 3, c = lin & 7;
        *(uint4*)&Qs[row][4 * c] =
            *(const uint4*)&QKV[(bb + qb + row) * QKV_N + hq + 8 * c];
    }
    __syncthreads();

    uint32_t qa[4][4];
    {
        const uint32_t qbase = smem_u32(Qs);
        const int mi = lane >> 3, mr = lane & 7;
        const int rowoff = (mi & 1) * 8, koff = (mi >> 1) * 4;
#pragma unroll
        for (int km = 0; km < 4; km++)
            ldsm4(qa[km], qbase + (uint32_t)((r0 + rowoff + mr) * 36 + km * 8 + koff) * 4);
    }

    float o[8][4];
#pragma unroll
    for (int j = 0; j < 8; j++)
#pragma unroll
        for (int q = 0; q < 4; q++) o[j][q] = 0.f;
    float m_g = -1e30f, m_g8 = -1e30f, l_g = 0.f, l_g8 = 0.f;
    const float SC = 0.18033688011112042f;  // (1/8) * log2(e)

    const uint32_t kbase = smem_u32(Ks), vbase = smem_u32(Vt);
    const int mi = lane >> 3, mr = lane & 7;

    const int nkt = 2 * qt + 2;
    for (int kt = 0; kt < nkt; kt++) {
        const int k0 = kt * 64;
#pragma unroll
        for (int r = 0; r < 2; r++) {
            const int lin = tid + 256 * r;
            const int row = lin >> 3, c = lin & 7;
            *(uint4*)&Ks[row][4 * c] =
                *(const uint4*)&QKV[(bb + k0 + row) * QKV_N + hk + 8 * c];
        }
        {
            const int kp = tid & 31, d8 = (tid >> 5) * 8;
            const __half* v0p = &QKV[(bb + k0 + 2 * kp) * QKV_N + hv + d8];
            uint4 v0 = *(const uint4*)v0p;
            uint4 v1 = *(const uint4*)(v0p + QKV_N);
            const ushort* a0 = (const ushort*)&v0;
            const ushort* a1 = (const ushort*)&v1;
#pragma unroll
            for (int i = 0; i < 8; i++)
                Vt[d8 + i][kp] = (uint32_t)a0[i] | ((uint32_t)a1[i] << 16);
        }
        __syncthreads();

        float s[8][4];
#pragma unroll
        for (int j = 0; j < 8; j++) {
            uint32_t kb[8];
            const uint32_t ab = kbase + (uint32_t)((8 * j + mr) * 36 + mi * 4) * 4;
            ldsm4(kb, ab);
            ldsm4(kb + 4, ab + 64);
            s[j][0] = s[j][1] = s[j][2] = s[j][3] = 0.f;
            mma_f16(s[j], qa[0], kb[0], kb[1]);
            mma_f16(s[j], qa[1], kb[2], kb[3]);
            mma_f16(s[j], qa[2], kb[4], kb[5]);
            mma_f16(s[j], qa[3], kb[6], kb[7]);
        }

        if (kt >= 2 * qt) {
            const int rg = qb + r0 + g;
#pragma unroll
            for (int j = 0; j < 8; j++) {
                const int col = k0 + 8 * j + 2 * t;
                if (col     > rg)     s[j][0] = -1e30f;
                if (col + 1 > rg)     s[j][1] = -1e30f;
                if (col     > rg + 8) s[j][2] = -1e30f;
                if (col + 1 > rg + 8) s[j][3] = -1e30f;
            }
        }

        float mg = -1e30f, mg8 = -1e30f;
#pragma unroll
        for (int j = 0; j < 8; j++) {
            mg  = fmaxf(mg,  fmaxf(s[j][0], s[j][1]));
            mg8 = fmaxf(mg8, fmaxf(s[j][2], s[j][3]));
        }
        mg  = fmaxf(mg,  __shfl_xor_sync(0xffffffffu, mg, 1));
        mg  = fmaxf(mg,  __shfl_xor_sync(0xffffffffu, mg, 2));
        mg8 = fmaxf(mg8, __shfl_xor_sync(0xffffffffu, mg8, 1));
        mg8 = fmaxf(mg8, __shfl_xor_sync(0xffffffffu, mg8, 2));
        const float mng  = fmaxf(m_g, mg);
        const float mng8 = fmaxf(m_g8, mg8);
        const float corr  = fast_ex2((m_g  - mng)  * SC);
        const float corr8 = fast_ex2((m_g8 - mng8) * SC);
        const float c1 = mng * SC, c2 = mng8 * SC;

        uint32_t pa[4][4];
        float sg = 0.f, sg8 = 0.f;
#pragma unroll
        for (int km = 0; km < 4; km++) {
#pragma unroll
            for (int jj = 0; jj < 2; jj++) {
                const int j = 2 * km + jj;
                uint32_t p01 = h2ex2(f22h2(s[j][0] * SC - c1, s[j][1] * SC - c1));
                uint32_t p23 = h2ex2(f22h2(s[j][2] * SC - c2, s[j][3] * SC - c2));
                pa[km][2 * jj]     = p01;
                pa[km][2 * jj + 1] = p23;
                float2 f01 = __half22float2(*(__half2*)&p01);
                float2 f23 = __half22float2(*(__half2*)&p23);
                sg  += f01.x + f01.y;
                sg8 += f23.x + f23.y;
            }
        }
        sg  += __shfl_xor_sync(0xffffffffu, sg, 1);
        sg  += __shfl_xor_sync(0xffffffffu, sg, 2);
        sg8 += __shfl_xor_sync(0xffffffffu, sg8, 1);
        sg8 += __shfl_xor_sync(0xffffffffu, sg8, 2);
        l_g  = l_g  * corr  + sg;
        l_g8 = l_g8 * corr8 + sg8;
        m_g = mng; m_g8 = mng8;
#pragma unroll
        for (int j = 0; j < 8; j++) {
            o[j][0] *= corr;  o[j][1] *= corr;
            o[j][2] *= corr8; o[j][3] *= corr8;
        }

#pragma unroll
        for (int j = 0; j < 8; j++) {
            uint32_t vb[8];
            const uint32_t ab = vbase + (uint32_t)((8 * j + mr) * 36 + mi * 4) * 4;
            ldsm4(vb, ab);
            ldsm4(vb + 4, ab + 64);
            mma_f16(o[j], pa[0], vb[0], vb[1]);
            mma_f16(o[j], pa[1], vb[2], vb[3]);
            mma_f16(o[j], pa[2], vb[4], vb[5]);
            mma_f16(o[j], pa[3], vb[6], vb[7]);
        }
        __syncthreads();
    }

    const float ig = 1.0f / l_g, ig8 = 1.0f / l_g8;
    __half* Og = Oh + (bb + qb + r0) * D_MODEL + hq;
#pragma unroll
    for (int j = 0; j < 8; j++) {
        const int col = 8 * j + 2 * t;
        *(__half2*)&Og[(size_t)g * D_MODEL + col] =
            __floats2half2_rn(o[j][0] * ig, o[j][1] * ig);
        *(__half2*)&Og[(size_t)(g + 8) * D_MODEL + col] =
            __floats2half2_rn(o[j][2] * ig8, o[j][3] * ig8);
    }
}

// ---------------- launch ----------------
extern "C" void kernel_launch(void* const* d_in, const int* in_sizes, int n_in,
                              void* d_out, int out_size)
{
    const float* x    = (const float*)d_in[0];
    const float* ln1s = (const float*)d_in[2];
    const float* ln1b = (const float*)d_in[3];
    const float* wq = (const float*)d_in[4];  const float* bq = (const float*)d_in[5];
    const float* wk = (const float*)d_in[6];  const float* bk = (const float*)d_in[7];
    const float* wv = (const float*)d_in[8];  const float* bv = (const float*)d_in[9];
    const float* wo = (const float*)d_in[10]; const float* bo = (const float*)d_in[11];
    const float* ln2s = (const float*)d_in[12];
    const float* ln2b = (const float*)d_in[13];
    const float* w1 = (const float*)d_in[14]; const float* b1 = (const float*)d_in[15];
    const float* w2 = (const float*)d_in[16]; const float* b2 = (const float*)d_in[17];
    float* out = (float*)d_out;

    __half *h1, *qkv, *att, *ff, *wqkvT, *woT, *w1T, *w2T;
    float *res;
    cudaGetSymbolAddress((void**)&h1,   g_h1);
    cudaGetSymbolAddress((void**)&qkv,  g_qkv);
    cudaGetSymbolAddress((void**)&att,  g_att);
    cudaGetSymbolAddress((void**)&res,  g_res);
    cudaGetSymbolAddress((void**)&ff,   g_ff);
    cudaGetSymbolAddress((void**)&wqkvT, g_wqkvT);
    cudaGetSymbolAddress((void**)&woT,  g_woT);
    cudaGetSymbolAddress((void**)&w1T,  g_w1T);
    cudaGetSymbolAddress((void**)&w2T,  g_w2T);

    cudaFuncSetAttribute(gemm_h_kernel<1>, cudaFuncAttributeMaxDynamicSharedMemorySize, GEMM_SMEM);
    cudaFuncSetAttribute(gemm_h_kernel<2>, cudaFuncAttributeMaxDynamicSharedMemorySize, GEMM_SMEM);
    cudaFuncSetAttribute(gemm_h_kernel<3>, cudaFuncAttributeMaxDynamicSharedMemorySize, GEMM_SMEM);

    // side stream for weight transposes (fork/join under graph capture)
    cudaStream_t side;
    cudaStreamCreateWithFlags(&side, cudaStreamNonBlocking);
    cudaEvent_t ev0, ev1, ev2;
    cudaEventCreateWithFlags(&ev0, cudaEventDisableTiming);
    cudaEventCreateWithFlags(&ev1, cudaEventDisableTiming);
    cudaEventCreateWithFlags(&ev2, cudaEventDisableTiming);

    const dim3 tb(32, 8);
    const dim3 gQKV(QKV_N / 128, MROWS / 128);   // (24, 64)
    const dim3 gD(D_MODEL / 128, MROWS / 128);   // (8, 64)
    const dim3 gF(DFF / 128,     MROWS / 128);   // (32, 64)

    cudaEventRecord(ev0, 0);
    cudaStreamWaitEvent(side, ev0, 0);
    // side stream: all 6 transposes
    transpose_h_kernel<<<dim3(D_MODEL / 32, D_MODEL / 32), tb, 0, side>>>(wq, wqkvT, D_MODEL, D_MODEL);
    transpose_h_kernel<<<dim3(D_MODEL / 32, D_MODEL / 32), tb, 0, side>>>(wk, wqkvT + (size_t)D_MODEL * D_MODEL, D_MODEL, D_MODEL);
    transpose_h_kernel<<<dim3(D_MODEL / 32, D_MODEL / 32), tb, 0, side>>>(wv, wqkvT + (size_t)2 * D_MODEL * D_MODEL, D_MODEL, D_MODEL);
    cudaEventRecord(ev1, side);
    transpose_h_kernel<<<dim3(D_MODEL / 32, D_MODEL / 32), tb, 0, side>>>(wo, woT, D_MODEL, D_MODEL);
    transpose_h_kernel<<<dim3(DFF / 32, D_MODEL / 32), tb, 0, side>>>(w1, w1T, D_MODEL, DFF);
    transpose_h_kernel<<<dim3(D_MODEL / 32, DFF / 32), tb, 0, side>>>(w2, w2T, DFF, D_MODEL);
    cudaEventRecord(ev2, side);

    // main stream
    ln_kernel<<<MROWS, 256>>>(x, ln1s, ln1b, h1);
    cudaStreamWaitEvent(0, ev1, 0);
    gemm_h_kernel<3><<<gQKV, 256, GEMM_SMEM>>>(h1, wqkvT, bq, bk, bv, nullptr, qkv, MROWS, QKV_N, D_MODEL);
    attn_tc_kernel<<<dim3(T_SEQ / 128, BATCH * NHEAD), 256>>>(qkv, att);
    cudaStreamWaitEvent(0, ev2, 0);
    gemm_h_kernel<1><<<gD, 256, GEMM_SMEM>>>(att, woT, bo, nullptr, nullptr, x, res, MROWS, D_MODEL, D_MODEL);
    ln_kernel<<<MROWS, 256>>>(res, ln2s, ln2b, h1);
    gemm_h_kernel<2><<<gF, 256, GEMM_SMEM>>>(h1, w1T, b1, nullptr, nullptr, nullptr, ff, MROWS, DFF, D_MODEL);
    gemm_h_kernel<1><<<gD, 256, GEMM_SMEM>>>(ff, w2T, b2, nullptr, nullptr, res, out, MROWS, D_MODEL, DFF);
}